// round 6
// baseline (speedup 1.0000x reference)
#include <cuda_runtime.h>
#include <math.h>

#define Bv 4
#define Vv 8
#define Hh 128
#define Ww 128
#define Cc 64
#define HW (Hh*Ww)
#define NIMG (Bv*Vv)
#define VP (Vv-1)
#define NBJ (Bv*VP)

__device__ float g_feats[NIMG*Cc*HW];   // fused features, NCHW
__device__ float g_mid[NIMG*Cc*HW];     // gelu(conv1), NCHW
__device__ int   g_src[NBJ*HW];
__device__ float g_wgt[NBJ];
__device__ float g_cam[NBJ*24];         // Einv rows0-2 (12) + K (9)

// ---------------------------------------------------------------------------
// Kernel 1: per-(b,j) camera precompute. Store Einv (rows 0-2) and K separately
// so the per-pixel math reproduces JAX's cam->proj sequence exactly.
// ---------------------------------------------------------------------------
__global__ void k_prep(const float* __restrict__ intr, const float* __restrict__ extr)
{
    int t = threadIdx.x;
    if (t >= NBJ) return;
    int b = t / VP, j = t % VP, k = j + 1;
    const float* E = extr + (b*Vv + k)*16;
    const float* K = intr + (b*Vv + k)*9;
    float m[16], inv[16];
    #pragma unroll
    for (int i = 0; i < 16; ++i) m[i] = E[i];

    inv[0]  =  m[5]*m[10]*m[15] - m[5]*m[11]*m[14] - m[9]*m[6]*m[15] + m[9]*m[7]*m[14] + m[13]*m[6]*m[11] - m[13]*m[7]*m[10];
    inv[4]  = -m[4]*m[10]*m[15] + m[4]*m[11]*m[14] + m[8]*m[6]*m[15] - m[8]*m[7]*m[14] - m[12]*m[6]*m[11] + m[12]*m[7]*m[10];
    inv[8]  =  m[4]*m[9]*m[15]  - m[4]*m[11]*m[13] - m[8]*m[5]*m[15] + m[8]*m[7]*m[13] + m[12]*m[5]*m[11] - m[12]*m[7]*m[9];
    inv[12] = -m[4]*m[9]*m[14]  + m[4]*m[10]*m[13] + m[8]*m[5]*m[14] - m[8]*m[6]*m[13] - m[12]*m[5]*m[10] + m[12]*m[6]*m[9];
    inv[1]  = -m[1]*m[10]*m[15] + m[1]*m[11]*m[14] + m[9]*m[2]*m[15] - m[9]*m[3]*m[14] - m[13]*m[2]*m[11] + m[13]*m[3]*m[10];
    inv[5]  =  m[0]*m[10]*m[15] - m[0]*m[11]*m[14] - m[8]*m[2]*m[15] + m[8]*m[3]*m[14] + m[12]*m[2]*m[11] - m[12]*m[3]*m[10];
    inv[9]  = -m[0]*m[9]*m[15]  + m[0]*m[11]*m[13] + m[8]*m[1]*m[15] - m[8]*m[3]*m[13] - m[12]*m[1]*m[11] + m[12]*m[3]*m[9];
    inv[13] =  m[0]*m[9]*m[14]  - m[0]*m[10]*m[13] - m[8]*m[1]*m[14] + m[8]*m[2]*m[13] + m[12]*m[1]*m[10] - m[12]*m[2]*m[9];
    inv[2]  =  m[1]*m[6]*m[15]  - m[1]*m[7]*m[14]  - m[5]*m[2]*m[15] + m[5]*m[3]*m[14] + m[13]*m[2]*m[7]  - m[13]*m[3]*m[6];
    inv[6]  = -m[0]*m[6]*m[15]  + m[0]*m[7]*m[14]  + m[4]*m[2]*m[15] - m[4]*m[3]*m[14] - m[12]*m[2]*m[7]  + m[12]*m[3]*m[6];
    inv[10] =  m[0]*m[5]*m[15]  - m[0]*m[7]*m[13]  - m[4]*m[1]*m[15] + m[4]*m[3]*m[13] + m[12]*m[1]*m[7]  - m[12]*m[3]*m[5];
    inv[14] = -m[0]*m[5]*m[14]  + m[0]*m[6]*m[13]  + m[4]*m[1]*m[14] - m[4]*m[2]*m[13] - m[12]*m[1]*m[6]  + m[12]*m[2]*m[5];
    inv[3]  = -m[1]*m[6]*m[11]  + m[1]*m[7]*m[10]  + m[5]*m[2]*m[11] - m[5]*m[3]*m[10] - m[9]*m[2]*m[7]   + m[9]*m[3]*m[6];
    inv[7]  =  m[0]*m[6]*m[11]  - m[0]*m[7]*m[10]  - m[4]*m[2]*m[11] + m[4]*m[3]*m[10] + m[8]*m[2]*m[7]   - m[8]*m[3]*m[6];
    inv[11] = -m[0]*m[5]*m[11]  + m[0]*m[7]*m[9]   + m[4]*m[1]*m[11] - m[4]*m[3]*m[9]  - m[8]*m[1]*m[7]   + m[8]*m[3]*m[5];
    inv[15] =  m[0]*m[5]*m[10]  - m[0]*m[6]*m[9]   - m[4]*m[1]*m[10] + m[4]*m[2]*m[9]  + m[8]*m[1]*m[6]   - m[8]*m[2]*m[5];

    float det = m[0]*inv[0] + m[1]*inv[4] + m[2]*inv[8] + m[3]*inv[12];
    float id = 1.0f / det;
    #pragma unroll
    for (int i = 0; i < 16; ++i) inv[i] *= id;

    float* o = g_cam + t*24;
    #pragma unroll
    for (int i = 0; i < 12; ++i) o[i] = inv[i];
    #pragma unroll
    for (int i = 0; i < 9; ++i) o[12 + i] = K[i];
}

// ---------------------------------------------------------------------------
// Kernel 2: projection -> gather index + mask count. Mirrors JAX rounding:
// cam = Einv*[p,1]; proj = K*cam (plain mul/add, no fma contraction); ndc.
// ---------------------------------------------------------------------------
__global__ void k_count(const float* __restrict__ means)
{
    int bj = blockIdx.x;
    int b = bj / VP, j = bj % VP;
    __shared__ float cm[24];
    __shared__ int s_cnt;
    if (threadIdx.x < 24) cm[threadIdx.x] = g_cam[bj*24 + threadIdx.x];
    if (threadIdx.x == 0) s_cnt = 0;
    __syncthreads();
    const float* mb = means + (size_t)(b*Vv + j)*HW*3;
    int cnt = 0;
    for (int i = threadIdx.x; i < HW; i += blockDim.x) {
        float x = mb[i*3+0], y = mb[i*3+1], z = mb[i*3+2];
        float c0 = __fadd_rn(__fadd_rn(__fadd_rn(__fmul_rn(cm[0],x), __fmul_rn(cm[1],y)), __fmul_rn(cm[2],z)), cm[3]);
        float c1 = __fadd_rn(__fadd_rn(__fadd_rn(__fmul_rn(cm[4],x), __fmul_rn(cm[5],y)), __fmul_rn(cm[6],z)), cm[7]);
        float c2 = __fadd_rn(__fadd_rn(__fadd_rn(__fmul_rn(cm[8],x), __fmul_rn(cm[9],y)), __fmul_rn(cm[10],z)), cm[11]);
        float p0 = __fadd_rn(__fadd_rn(__fmul_rn(cm[12],c0), __fmul_rn(cm[13],c1)), __fmul_rn(cm[14],c2));
        float p1 = __fadd_rn(__fadd_rn(__fmul_rn(cm[15],c0), __fmul_rn(cm[16],c1)), __fmul_rn(cm[17],c2));
        float p2 = __fadd_rn(__fadd_rn(__fmul_rn(cm[18],c0), __fmul_rn(cm[19],c1)), __fmul_rn(cm[20],c2));
        float d  = __fadd_rn(p2, 1e-8f);
        float nx = p0 / d, ny = p1 / d;
        bool valid = (nx >= 0.f) && (nx < 1.f) && (ny >= 0.f) && (ny < 1.f) && (c2 > 1e-8f);
        int px = (int)floorf(__fmul_rn(nx, (float)Ww)); px = min(max(px, 0), Ww-1);
        int py = (int)floorf(__fmul_rn(ny, (float)Hh)); py = min(max(py, 0), Hh-1);
        g_src[bj*HW + i] = valid ? (py*Ww + px) : -1;
        cnt += valid ? 1 : 0;
    }
    atomicAdd(&s_cnt, cnt);
    __syncthreads();
    if (threadIdx.x == 0) g_wgt[bj] = (0.1f / (float)HW) * (float)s_cnt;
}

// ---------------------------------------------------------------------------
// Kernel 3: fuse + transpose NHWC->NCHW into g_feats.
// ---------------------------------------------------------------------------
__global__ __launch_bounds__(256)
void k_fuse(const float* __restrict__ gsf)
{
    int xseg = blockIdx.x, y = blockIdx.y, n = blockIdx.z;
    int b = n >> 3, view = n & 7;
    int x0 = xseg * 64;
    __shared__ int   S[64];
    __shared__ float s_wv;
    __shared__ float comb[64*65];
    int tid = threadIdx.x;
    if (view < VP) {
        int bj = b*VP + view;
        if (tid < 64) S[tid] = g_src[bj*HW + y*Ww + x0 + tid];
        if (tid == 0) s_wv = g_wgt[bj];
    } else {
        if (tid < 64) S[tid] = -1;
        if (tid == 0) s_wv = 0.f;
    }
    __syncthreads();
    float wg = s_wv;
    float iw = 1.0f / (1.0f + wg);
    size_t fj = ((size_t)n*HW + (size_t)y*Ww + x0) * Cc;
    size_t fk = (size_t)(n+1) * HW * Cc;
    #pragma unroll
    for (int it = 0; it < 4; ++it) {
        int px = (tid >> 4) + it*16;
        int c4 = (tid & 15) * 4;
        float4 a = *(const float4*)(gsf + fj + (size_t)px*Cc + c4);
        int s = S[px];
        float4 g = make_float4(0.f, 0.f, 0.f, 0.f);
        if (s >= 0) g = *(const float4*)(gsf + fk + (size_t)s*Cc + c4);
        float4 r;
        r.x = (a.x + g.x*wg) * iw;
        r.y = (a.y + g.y*wg) * iw;
        r.z = (a.z + g.z*wg) * iw;
        r.w = (a.w + g.w*wg) * iw;
        comb[(c4+0)*65 + px] = r.x;
        comb[(c4+1)*65 + px] = r.y;
        comb[(c4+2)*65 + px] = r.z;
        comb[(c4+3)*65 + px] = r.w;
    }
    __syncthreads();
    int x = tid & 63, cb = tid >> 6;
    #pragma unroll
    for (int k = 0; k < 16; ++k) {
        int c = cb*16 + k;
        g_feats[((n*Cc + c)*Hh + y)*Ww + x0 + x] = comb[c*65 + x];
    }
}

// ---------------------------------------------------------------------------
// Packed fp32x2 helpers
// ---------------------------------------------------------------------------
typedef unsigned long long ull;
__device__ __forceinline__ ull pk2(float lo, float hi) {
    ull r;
    asm("mov.b64 %0, {%1, %2};" : "=l"(r) : "f"(lo), "f"(hi));
    return r;
}
__device__ __forceinline__ void upk2(ull v, float& lo, float& hi) {
    asm("mov.b64 {%0, %1}, %2;" : "=f"(lo), "=f"(hi) : "l"(v));
}
__device__ __forceinline__ void fma2(ull& d, ull a, ull b) {
    asm("fma.rn.f32x2 %0, %1, %2, %0;" : "+l"(d) : "l"(a), "l"(b));
}

// ---------------------------------------------------------------------------
// Kernel 4/5: 3x3 SAME conv, NCHW in. Weight-stationary (8 oc per block),
// f32x2 packed over OC-PAIRS (weight pairs load directly as LDS.64 broadcast,
// no duplication MOVs). Tile 32x32 px, ic chunked by 2, double-buffered input.
// Thread: 4 consecutive px x 4 oc-pairs (all 8 oc). 256 threads.
// ---------------------------------------------------------------------------
#define PITCH 35
template<bool GELU, bool NHWC_OUT>
__global__ __launch_bounds__(256, 3)
void k_conv(const float* __restrict__ in, const float* __restrict__ w,
            const float* __restrict__ bias, float* __restrict__ out)
{
    __shared__ float s_w[64*9*8];            // [ic][tap][oc_local] 18432B
    __shared__ float s_in[2*2*34*PITCH];     // [buf][ic][row34][PITCH] 19040B

    int ocg = blockIdx.x;            // 8 consecutive blocks share input tile
    int tile = blockIdx.y;
    int n    = blockIdx.z;
    int x0 = (tile & 3) * 32, y0 = (tile >> 2) * 32;
    int oc0 = ocg * 8;
    int tid = threadIdx.x;
    int prow = tid >> 3;             // 0..31
    int xg   = (tid & 7) * 4;        // 0,4,...,28

    // Load stationary weights: s_w[(ic*9+tap)*8 + ocl] = w[(oc0+ocl)*576 + ic*9 + tap]
    #pragma unroll
    for (int i = 0; i < 18; ++i) {
        int idx = tid + i*256;       // 0..4607
        int ict = idx >> 3, ocl = idx & 7;   // ict = ic*9+tap
        int ic = ict / 9, tap = ict - ic*9;
        s_w[idx] = w[(oc0 + ocl)*576 + ic*9 + tap];
    }

    const float* inb = in + (size_t)n*64*HW;

    // Load chunk 0 (ic 0,1) into buffer 0
    #pragma unroll
    for (int i = 0; i < 10; ++i) {
        int idx = tid + i*256;
        if (idx < 2312) {
            int ic = idx / 1156; int rem = idx - ic*1156;
            int rr = rem / 34, cc = rem - rr*34;
            int gy = y0 + rr - 1, gx = x0 + cc - 1;
            float v = 0.f;
            if ((unsigned)gy < 128u && (unsigned)gx < 128u)
                v = inb[(ic*128 + gy)*128 + gx];
            s_in[(ic*34 + rr)*PITCH + cc] = v;
        }
    }
    __syncthreads();

    ull acc[4][4];   // [oc_pair][px]
    #pragma unroll
    for (int o = 0; o < 4; ++o)
        #pragma unroll
        for (int p = 0; p < 4; ++p) acc[o][p] = 0ULL;

    #pragma unroll 1
    for (int ch = 0; ch < 32; ++ch) {
        // Prefetch next chunk into registers
        float pf[10];
        if (ch < 31) {
            int icb = (ch + 1) * 2;
            #pragma unroll
            for (int i = 0; i < 10; ++i) {
                int idx = tid + i*256;
                pf[i] = 0.f;
                if (idx < 2312) {
                    int ic = idx / 1156; int rem = idx - ic*1156;
                    int rr = rem / 34, cc = rem - rr*34;
                    int gy = y0 + rr - 1, gx = x0 + cc - 1;
                    if ((unsigned)gy < 128u && (unsigned)gx < 128u)
                        pf[i] = inb[((icb + ic)*128 + gy)*128 + gx];
                }
            }
        }
        // Compute on current buffer
        const float* sb = &s_in[(ch & 1) * (2*34*PITCH)];
        #pragma unroll
        for (int ic = 0; ic < 2; ++ic) {
            int icg = ch*2 + ic;
            #pragma unroll
            for (int ky = 0; ky < 3; ++ky) {
                const float* ip = &sb[(ic*34 + prow + ky)*PITCH + xg];
                float v0 = ip[0], v1 = ip[1], v2 = ip[2], v3 = ip[3], v4 = ip[4], v5 = ip[5];
                ull d0 = pk2(v0,v0), d1 = pk2(v1,v1), d2 = pk2(v2,v2);
                ull d3 = pk2(v3,v3), d4 = pk2(v4,v4), d5 = pk2(v5,v5);
                #pragma unroll
                for (int kx = 0; kx < 3; ++kx) {
                    const ull* wp = (const ull*)&s_w[(icg*9 + ky*3 + kx)*8];
                    ull w0 = wp[0], w1 = wp[1], w2 = wp[2], w3 = wp[3];
                    ull e0 = (kx==0) ? d0 : (kx==1) ? d1 : d2;
                    ull e1 = (kx==0) ? d1 : (kx==1) ? d2 : d3;
                    ull e2 = (kx==0) ? d2 : (kx==1) ? d3 : d4;
                    ull e3 = (kx==0) ? d3 : (kx==1) ? d4 : d5;
                    fma2(acc[0][0], w0, e0); fma2(acc[0][1], w0, e1);
                    fma2(acc[0][2], w0, e2); fma2(acc[0][3], w0, e3);
                    fma2(acc[1][0], w1, e0); fma2(acc[1][1], w1, e1);
                    fma2(acc[1][2], w1, e2); fma2(acc[1][3], w1, e3);
                    fma2(acc[2][0], w2, e0); fma2(acc[2][1], w2, e1);
                    fma2(acc[2][2], w2, e2); fma2(acc[2][3], w2, e3);
                    fma2(acc[3][0], w3, e0); fma2(acc[3][1], w3, e1);
                    fma2(acc[3][2], w3, e2); fma2(acc[3][3], w3, e3);
                }
            }
        }
        // Commit prefetched chunk into the other buffer
        if (ch < 31) {
            float* sn = &s_in[((ch + 1) & 1) * (2*34*PITCH)];
            #pragma unroll
            for (int i = 0; i < 10; ++i) {
                int idx = tid + i*256;
                if (idx < 2312) {
                    int ic = idx / 1156; int rem = idx - ic*1156;
                    int rr = rem / 34, cc = rem - rr*34;
                    sn[(ic*34 + rr)*PITCH + cc] = pf[i];
                }
            }
            __syncthreads();
        }
    }

    // Epilogue
    float r[8][4];
    #pragma unroll
    for (int o = 0; o < 4; ++o)
        #pragma unroll
        for (int p = 0; p < 4; ++p)
            upk2(acc[o][p], r[2*o][p], r[2*o+1][p]);
    #pragma unroll
    for (int o = 0; o < 8; ++o) {
        float bv = bias[oc0 + o];
        #pragma unroll
        for (int p = 0; p < 4; ++p) {
            float a = r[o][p] + bv;
            if (GELU) a = 0.5f * a * (1.0f + erff(a * 0.70710678118654752f));
            r[o][p] = a;
        }
    }
    int gy = y0 + prow, gx = x0 + xg;
    if (!NHWC_OUT) {
        #pragma unroll
        for (int o = 0; o < 8; ++o)
            *(float4*)&out[(((size_t)n*64 + oc0 + o)*128 + gy)*128 + gx] =
                make_float4(r[o][0], r[o][1], r[o][2], r[o][3]);
    } else {
        #pragma unroll
        for (int p = 0; p < 4; ++p) {
            size_t p0 = ((size_t)(n*HW) + (size_t)gy*128 + gx + p)*64 + oc0;
            *(float4*)&out[p0]     = make_float4(r[0][p], r[1][p], r[2][p], r[3][p]);
            *(float4*)&out[p0 + 4] = make_float4(r[4][p], r[5][p], r[6][p], r[7][p]);
        }
    }
}

// ---------------------------------------------------------------------------
extern "C" void kernel_launch(void* const* d_in, const int* in_sizes, int n_in,
                              void* d_out, int out_size)
{
    const float* means = (const float*)d_in[0];
    const float* gsf   = (const float*)d_in[2];
    const float* intr  = (const float*)d_in[3];
    const float* extr  = (const float*)d_in[4];
    const float* w1    = (const float*)d_in[5];
    const float* b1    = (const float*)d_in[6];
    const float* w2    = (const float*)d_in[7];
    const float* b2    = (const float*)d_in[8];
    float* out = (float*)d_out;

    float *pf = nullptr, *pm = nullptr;
    cudaGetSymbolAddress((void**)&pf, g_feats);
    cudaGetSymbolAddress((void**)&pm, g_mid);

    k_prep<<<1, 32>>>(intr, extr);
    k_count<<<NBJ, 256>>>(means);
    k_fuse<<<dim3(2, 128, 32), 256>>>(gsf);
    k_conv<true,  false><<<dim3(8, 16, 32), 256>>>(pf, w1, b1, pm);
    k_conv<false, true ><<<dim3(8, 16, 32), 256>>>(pm, w2, b2, out);
}

// round 8
// speedup vs baseline: 3.5094x; 3.5094x over previous
#include <cuda_runtime.h>
#include <cuda_bf16.h>
#include <math.h>
#include <stdint.h>

#define Bv 4
#define Vv 8
#define HW 16384
#define VP 7
#define NBJ 28
#define NIMG 32
typedef unsigned long long u64;
typedef uint32_t u32;

// ------------------------- device scratch -------------------------
__device__ __nv_bfloat16 g_fh[NIMG*HW*64];
__device__ __nv_bfloat16 g_fl[NIMG*HW*64];
__device__ __nv_bfloat16 g_mh[NIMG*HW*64];
__device__ __nv_bfloat16 g_ml[NIMG*HW*64];
__device__ __nv_bfloat16 g_wh[2*9*64*64];   // [layer][tap][ic][oc]
__device__ __nv_bfloat16 g_wl[2*9*64*64];
__device__ int   g_src[NBJ*HW];
__device__ float g_wgt[NBJ];
__device__ float g_cam[NBJ*24];

// ------------------------- PTX helpers -------------------------
__device__ __forceinline__ u32 s2u(const void* p) {
    u32 a;
    asm("{ .reg .u64 t; cvta.to.shared.u64 t, %1; cvt.u32.u64 %0, t; }" : "=r"(a) : "l"(p));
    return a;
}
__device__ __forceinline__ void ldsm4(u32* r, u32 addr) {
    asm volatile("ldmatrix.sync.aligned.m8n8.x4.shared.b16 {%0,%1,%2,%3}, [%4];"
        : "=r"(r[0]), "=r"(r[1]), "=r"(r[2]), "=r"(r[3]) : "r"(addr));
}
__device__ __forceinline__ void ldsm4t(u32* r, u32 addr) {
    asm volatile("ldmatrix.sync.aligned.m8n8.x4.trans.shared.b16 {%0,%1,%2,%3}, [%4];"
        : "=r"(r[0]), "=r"(r[1]), "=r"(r[2]), "=r"(r[3]) : "r"(addr));
}
__device__ __forceinline__ void mma_bf16(float* d, const u32* a, const u32* b) {
    asm volatile("mma.sync.aligned.m16n8k16.row.col.f32.bf16.bf16.f32 "
        "{%0,%1,%2,%3}, {%4,%5,%6,%7}, {%8,%9}, {%0,%1,%2,%3};"
        : "+f"(d[0]), "+f"(d[1]), "+f"(d[2]), "+f"(d[3])
        : "r"(a[0]), "r"(a[1]), "r"(a[2]), "r"(a[3]), "r"(b[0]), "r"(b[1]));
}

// ---------------------------------------------------------------------------
// Kernel 1: camera precompute (proven — exact JAX mirror)
// ---------------------------------------------------------------------------
__global__ void k_prep(const float* __restrict__ intr, const float* __restrict__ extr)
{
    int t = threadIdx.x;
    if (t >= NBJ) return;
    int b = t / VP, j = t % VP, k = j + 1;
    const float* E = extr + (b*Vv + k)*16;
    const float* K = intr + (b*Vv + k)*9;
    float m[16], inv[16];
    #pragma unroll
    for (int i = 0; i < 16; ++i) m[i] = E[i];

    inv[0]  =  m[5]*m[10]*m[15] - m[5]*m[11]*m[14] - m[9]*m[6]*m[15] + m[9]*m[7]*m[14] + m[13]*m[6]*m[11] - m[13]*m[7]*m[10];
    inv[4]  = -m[4]*m[10]*m[15] + m[4]*m[11]*m[14] + m[8]*m[6]*m[15] - m[8]*m[7]*m[14] - m[12]*m[6]*m[11] + m[12]*m[7]*m[10];
    inv[8]  =  m[4]*m[9]*m[15]  - m[4]*m[11]*m[13] - m[8]*m[5]*m[15] + m[8]*m[7]*m[13] + m[12]*m[5]*m[11] - m[12]*m[7]*m[9];
    inv[12] = -m[4]*m[9]*m[14]  + m[4]*m[10]*m[13] + m[8]*m[5]*m[14] - m[8]*m[6]*m[13] - m[12]*m[5]*m[10] + m[12]*m[6]*m[9];
    inv[1]  = -m[1]*m[10]*m[15] + m[1]*m[11]*m[14] + m[9]*m[2]*m[15] - m[9]*m[3]*m[14] - m[13]*m[2]*m[11] + m[13]*m[3]*m[10];
    inv[5]  =  m[0]*m[10]*m[15] - m[0]*m[11]*m[14] - m[8]*m[2]*m[15] + m[8]*m[3]*m[14] + m[12]*m[2]*m[11] - m[12]*m[3]*m[10];
    inv[9]  = -m[0]*m[9]*m[15]  + m[0]*m[11]*m[13] + m[8]*m[1]*m[15] - m[8]*m[3]*m[13] - m[12]*m[1]*m[11] + m[12]*m[3]*m[9];
    inv[13] =  m[0]*m[9]*m[14]  - m[0]*m[10]*m[13] - m[8]*m[1]*m[14] + m[8]*m[2]*m[13] + m[12]*m[1]*m[10] - m[12]*m[2]*m[9];
    inv[2]  =  m[1]*m[6]*m[15]  - m[1]*m[7]*m[14]  - m[5]*m[2]*m[15] + m[5]*m[3]*m[14] + m[13]*m[2]*m[7]  - m[13]*m[3]*m[6];
    inv[6]  = -m[0]*m[6]*m[15]  + m[0]*m[7]*m[14]  + m[4]*m[2]*m[15] - m[4]*m[3]*m[14] - m[12]*m[2]*m[7]  + m[12]*m[3]*m[6];
    inv[10] =  m[0]*m[5]*m[15]  - m[0]*m[7]*m[13]  - m[4]*m[1]*m[15] + m[4]*m[3]*m[13] + m[12]*m[1]*m[7]  - m[12]*m[3]*m[5];
    inv[14] = -m[0]*m[5]*m[14]  + m[0]*m[6]*m[13]  + m[4]*m[1]*m[14] - m[4]*m[2]*m[13] - m[12]*m[1]*m[6]  + m[12]*m[2]*m[5];
    inv[3]  = -m[1]*m[6]*m[11]  + m[1]*m[7]*m[10]  + m[5]*m[2]*m[11] - m[5]*m[3]*m[10] - m[9]*m[2]*m[7]   + m[9]*m[3]*m[6];
    inv[7]  =  m[0]*m[6]*m[11]  - m[0]*m[7]*m[10]  - m[4]*m[2]*m[11] + m[4]*m[3]*m[10] + m[8]*m[2]*m[7]   - m[8]*m[3]*m[6];
    inv[11] = -m[0]*m[5]*m[11]  + m[0]*m[7]*m[9]   + m[4]*m[1]*m[11] - m[4]*m[3]*m[9]  - m[8]*m[1]*m[7]   + m[8]*m[3]*m[5];
    inv[15] =  m[0]*m[5]*m[10]  - m[0]*m[6]*m[9]   - m[4]*m[1]*m[10] + m[4]*m[2]*m[9]  + m[8]*m[1]*m[6]   - m[8]*m[2]*m[5];

    float det = m[0]*inv[0] + m[1]*inv[4] + m[2]*inv[8] + m[3]*inv[12];
    float id = 1.0f / det;
    #pragma unroll
    for (int i = 0; i < 16; ++i) inv[i] *= id;

    float* o = g_cam + t*24;
    #pragma unroll
    for (int i = 0; i < 12; ++i) o[i] = inv[i];
    #pragma unroll
    for (int i = 0; i < 9; ++i) o[12 + i] = K[i];
}

// ---------------------------------------------------------------------------
// Kernel 2: projection -> gather index + count (proven)
// ---------------------------------------------------------------------------
__global__ void k_count(const float* __restrict__ means)
{
    int bj = blockIdx.x;
    int b = bj / VP, j = bj % VP;
    __shared__ float cm[24];
    __shared__ int s_cnt;
    if (threadIdx.x < 24) cm[threadIdx.x] = g_cam[bj*24 + threadIdx.x];
    if (threadIdx.x == 0) s_cnt = 0;
    __syncthreads();
    const float* mb = means + (size_t)(b*Vv + j)*HW*3;
    int cnt = 0;
    for (int i = threadIdx.x; i < HW; i += blockDim.x) {
        float x = mb[i*3+0], y = mb[i*3+1], z = mb[i*3+2];
        float c0 = __fadd_rn(__fadd_rn(__fadd_rn(__fmul_rn(cm[0],x), __fmul_rn(cm[1],y)), __fmul_rn(cm[2],z)), cm[3]);
        float c1 = __fadd_rn(__fadd_rn(__fadd_rn(__fmul_rn(cm[4],x), __fmul_rn(cm[5],y)), __fmul_rn(cm[6],z)), cm[7]);
        float c2 = __fadd_rn(__fadd_rn(__fadd_rn(__fmul_rn(cm[8],x), __fmul_rn(cm[9],y)), __fmul_rn(cm[10],z)), cm[11]);
        float p0 = __fadd_rn(__fadd_rn(__fmul_rn(cm[12],c0), __fmul_rn(cm[13],c1)), __fmul_rn(cm[14],c2));
        float p1 = __fadd_rn(__fadd_rn(__fmul_rn(cm[15],c0), __fmul_rn(cm[16],c1)), __fmul_rn(cm[17],c2));
        float p2 = __fadd_rn(__fadd_rn(__fmul_rn(cm[18],c0), __fmul_rn(cm[19],c1)), __fmul_rn(cm[20],c2));
        float d  = __fadd_rn(p2, 1e-8f);
        float nx = p0 / d, ny = p1 / d;
        bool valid = (nx >= 0.f) && (nx < 1.f) && (ny >= 0.f) && (ny < 1.f) && (c2 > 1e-8f);
        int px = (int)floorf(__fmul_rn(nx, 128.f)); px = min(max(px, 0), 127);
        int py = (int)floorf(__fmul_rn(ny, 128.f)); py = min(max(py, 0), 127);
        g_src[bj*HW + i] = valid ? (py*128 + px) : -1;
        cnt += valid ? 1 : 0;
    }
    atomicAdd(&s_cnt, cnt);
    __syncthreads();
    if (threadIdx.x == 0) g_wgt[bj] = (0.1f / (float)HW) * (float)s_cnt;
}

// ---------------------------------------------------------------------------
// Kernel 3: weight split fp32 -> bf16 hi/lo, layout [layer][tap][ic][oc]
// ---------------------------------------------------------------------------
__global__ void k_wsplit(const float* __restrict__ w1, const float* __restrict__ w2)
{
    int idx = blockIdx.x*256 + threadIdx.x;
    if (idx >= 2*9*64*64) return;
    int layer = idx / 36864; int rem = idx - layer*36864;
    int tap = rem >> 12;
    int ic = (rem >> 6) & 63, oc = rem & 63;
    const float* w = layer ? w2 : w1;
    float v = w[(oc*64 + ic)*9 + tap];
    __nv_bfloat16 h = __float2bfloat16(v);
    g_wh[idx] = h;
    g_wl[idx] = __float2bfloat16(v - __bfloat162float(h));
}

// ---------------------------------------------------------------------------
// Kernel 4: fuse -> NHWC bf16 hi/lo planes
// ---------------------------------------------------------------------------
__global__ __launch_bounds__(256)
void k_fuse2(const float* __restrict__ gsf)
{
    int y = blockIdx.x, n = blockIdx.y;
    int b = n >> 3, view = n & 7;
    __shared__ int S[128];
    __shared__ float s_w;
    int tid = threadIdx.x;
    if (view < VP) {
        int bj = b*VP + view;
        if (tid < 128) S[tid] = g_src[bj*HW + y*128 + tid];
        if (tid == 0) s_w = g_wgt[bj];
    } else {
        if (tid < 128) S[tid] = -1;
        if (tid == 0) s_w = 0.f;
    }
    __syncthreads();
    float wg = s_w, iw = 1.f / (1.f + wg);
    const float* fj = gsf + ((size_t)n*HW + (size_t)y*128)*64;
    const float* fk = gsf + (size_t)(n+1)*HW*64;
    size_t ob = ((size_t)n*HW + (size_t)y*128)*64;
    #pragma unroll
    for (int i = 0; i < 8; ++i) {
        int idx = tid + i*256;
        int px = idx >> 4, c4 = (idx & 15)*4;
        float4 a = *(const float4*)(fj + px*64 + c4);
        int s = S[px];
        float4 g = make_float4(0.f,0.f,0.f,0.f);
        if (s >= 0) g = *(const float4*)(fk + (size_t)s*64 + c4);
        float v0 = (a.x + g.x*wg)*iw, v1 = (a.y + g.y*wg)*iw;
        float v2 = (a.z + g.z*wg)*iw, v3 = (a.w + g.w*wg)*iw;
        __nv_bfloat16 h0 = __float2bfloat16(v0), h1 = __float2bfloat16(v1);
        __nv_bfloat16 h2 = __float2bfloat16(v2), h3 = __float2bfloat16(v3);
        __nv_bfloat16 l0 = __float2bfloat16(v0 - __bfloat162float(h0));
        __nv_bfloat16 l1 = __float2bfloat16(v1 - __bfloat162float(h1));
        __nv_bfloat16 l2 = __float2bfloat16(v2 - __bfloat162float(h2));
        __nv_bfloat16 l3 = __float2bfloat16(v3 - __bfloat162float(h3));
        uint2 ph, pl;
        ph.x = (u32)__bfloat16_as_ushort(h0) | ((u32)__bfloat16_as_ushort(h1) << 16);
        ph.y = (u32)__bfloat16_as_ushort(h2) | ((u32)__bfloat16_as_ushort(h3) << 16);
        pl.x = (u32)__bfloat16_as_ushort(l0) | ((u32)__bfloat16_as_ushort(l1) << 16);
        pl.y = (u32)__bfloat16_as_ushort(l2) | ((u32)__bfloat16_as_ushort(l3) << 16);
        *(uint2*)(g_fh + ob + px*64 + c4) = ph;
        *(uint2*)(g_fl + ob + px*64 + c4) = pl;
    }
}

// ---------------------------------------------------------------------------
// Kernel 5/6: mma.sync bf16 3-term split conv. grid(2 ochalf, 2 slab, 32 img),
// 256 threads = 8 warps, warp tile 16px x 32oc.
// SMEM: B 18 tiles [64ic x 32oc] stride 80B = 92160B;
//       A ring 3 slots x 2 planes x [130 rows x 64ic] stride 144B = 112320B.
// ---------------------------------------------------------------------------
#define BTILE 5120u
#define AROW 144u
#define APLANE 18720u
#define ASLOT 37440u
#define BOFF_SZ 92160u
#define SMEM_REQ 204480

template<bool FIRST>
__global__ void __launch_bounds__(256, 1) k_conv_mma(
    const __nv_bfloat16* __restrict__ inh, const __nv_bfloat16* __restrict__ inl,
    const float* __restrict__ bias,
    __nv_bfloat16* __restrict__ outh, __nv_bfloat16* __restrict__ outl,
    float* __restrict__ outf,
    const __nv_bfloat16* __restrict__ wh, const __nv_bfloat16* __restrict__ wl)
{
    extern __shared__ char dsm[];
    u32 sb = s2u(dsm);
    u32 Boff = sb, Aoff = sb + BOFF_SZ;

    int ochalf = blockIdx.x, slab = blockIdx.y, n = blockIdx.z;
    int oc0 = ochalf*32, ybase = slab*64;
    int tid = threadIdx.x, wid = tid >> 5, t = tid & 31;
    int px0 = wid*16;

    // ---- B build: transpose-free vectorized copy into stride-80 rows ----
    #pragma unroll
    for (int i = 0; i < 18; ++i) {
        int c = tid + i*256;              // 4608 chunks of 16B
        int tp = c >> 8;                  // tap*2+plane
        int rem = c & 255;
        int ic = rem >> 2, q = rem & 3;
        const __nv_bfloat16* src = (tp & 1) ? wl : wh;
        int tap = tp >> 1;
        uint4 v = *(const uint4*)(src + ((size_t)tap*64 + ic)*64 + oc0 + q*8);
        *(uint4*)(dsm + (u32)tp*BTILE + (u32)ic*80u + (u32)q*16u) = v;
    }
    // ---- zero halo rows 0 and 129 of all 3 slots x 2 planes ----
    if (tid < 96) {
        int slot = tid / 32, rem = tid & 31;
        int plane = rem >> 4, rr = (rem >> 3) & 1, q = rem & 7;
        u32 off = BOFF_SZ + (u32)slot*ASLOT + (u32)plane*APLANE + (rr ? 129u*AROW : 0u) + (u32)q*16u;
        *(uint4*)(dsm + off) = make_uint4(0,0,0,0);
    }
    // ---- prologue: build rows ybase-1 .. ybase+1 ----
    for (int r = ybase-1; r <= ybase+1; ++r) {
        int slot = (r + 3) % 3;
        u32 base = BOFF_SZ + (u32)slot*ASLOT;
        bool vr = ((unsigned)r < 128u);
        #pragma unroll
        for (int i = 0; i < 8; ++i) {
            int c = tid + i*256;          // 2048 chunks
            int plane = c >> 10, rem = c & 1023, px = rem >> 3, q = rem & 7;
            uint4 v = make_uint4(0,0,0,0);
            if (vr) v = *(const uint4*)((plane ? inl : inh) + ((size_t)n*HW + (size_t)r*128 + px)*64 + q*8);
            *(uint4*)(dsm + base + (u32)plane*APLANE + (u32)(px+1)*AROW + (u32)q*16u) = v;
        }
    }
    // per-thread bias regs
    float bo0[4], bo1[4];
    #pragma unroll
    for (int nb = 0; nb < 4; ++nb) {
        int oc = oc0 + nb*8 + (t & 3)*2;
        bo0[nb] = bias[oc];
        bo1[nb] = bias[oc + 1];
    }
    __syncthreads();

    u32 laneA = (u32)(t & 15)*AROW + (u32)((t >> 4) << 4);
    u32 laneB = (u32)(t & 15)*80u  + (u32)((t >> 4) << 4);

    for (int y = 0; y < 64; ++y) {
        int gy = ybase + y;
        // ---- prefetch row gy+2 into regs ----
        uint4 pf[8];
        int g2 = gy + 2;
        bool v2 = (g2 <= 127);
        #pragma unroll
        for (int i = 0; i < 8; ++i) {
            int c = tid + i*256;
            int plane = c >> 10, rem = c & 1023, px = rem >> 3, q = rem & 7;
            pf[i] = make_uint4(0,0,0,0);
            if (v2) pf[i] = *(const uint4*)((plane ? inl : inh) + ((size_t)n*HW + (size_t)g2*128 + px)*64 + q*8);
        }
        // ---- k-loop ----
        float acc[4][4];
        #pragma unroll
        for (int nb = 0; nb < 4; ++nb)
            #pragma unroll
            for (int i = 0; i < 4; ++i) acc[nb][i] = 0.f;

        u32 aH[3];
        #pragma unroll
        for (int dy = 0; dy < 3; ++dy) {
            int r = gy - 1 + dy;
            aH[dy] = Aoff + (u32)((r + 3) % 3)*ASLOT;
        }
        #pragma unroll 1
        for (int dy = 0; dy < 3; ++dy) {
            #pragma unroll
            for (int dx = 0; dx < 3; ++dx) {
                u32 rowoff = (u32)(px0 + dx)*AROW + laneA;
                u32 ah = aH[dy] + rowoff;
                u32 al = ah + APLANE;
                u32 bb = Boff + (u32)((dy*3 + dx)*2)*BTILE + laneB;
                #pragma unroll
                for (int kc = 0; kc < 4; ++kc) {
                    u32 Ah[4], Al[4], Bh[8], Bl[8];
                    ldsm4(Ah, ah + kc*32);
                    ldsm4(Al, al + kc*32);
                    ldsm4t(Bh,     bb + kc*1280u);
                    ldsm4t(Bh + 4, bb + kc*1280u + 32u);
                    ldsm4t(Bl,     bb + BTILE + kc*1280u);
                    ldsm4t(Bl + 4, bb + BTILE + kc*1280u + 32u);
                    #pragma unroll
                    for (int nb = 0; nb < 4; ++nb) {
                        mma_bf16(acc[nb], Ah, &Bh[nb*2]);
                        mma_bf16(acc[nb], Al, &Bh[nb*2]);
                        mma_bf16(acc[nb], Ah, &Bl[nb*2]);
                    }
                }
            }
        }
        // ---- epilogue: bias (+gelu), store row gy ----
        #pragma unroll
        for (int nb = 0; nb < 4; ++nb) {
            int oc = oc0 + nb*8 + (t & 3)*2;
            #pragma unroll
            for (int rg = 0; rg < 2; ++rg) {
                int px = px0 + (t >> 2) + rg*8;
                float v0 = acc[nb][rg*2]   + bo0[nb];
                float v1 = acc[nb][rg*2+1] + bo1[nb];
                size_t base = ((size_t)n*HW + (size_t)gy*128 + px)*64 + oc;
                if (FIRST) {
                    v0 = 0.5f * v0 * (1.0f + erff(v0 * 0.70710678118654752f));
                    v1 = 0.5f * v1 * (1.0f + erff(v1 * 0.70710678118654752f));
                    __nv_bfloat16 h0 = __float2bfloat16(v0);
                    __nv_bfloat16 h1 = __float2bfloat16(v1);
                    __nv_bfloat16 l0 = __float2bfloat16(v0 - __bfloat162float(h0));
                    __nv_bfloat16 l1 = __float2bfloat16(v1 - __bfloat162float(h1));
                    u32 hp = (u32)__bfloat16_as_ushort(h0) | ((u32)__bfloat16_as_ushort(h1) << 16);
                    u32 lp = (u32)__bfloat16_as_ushort(l0) | ((u32)__bfloat16_as_ushort(l1) << 16);
                    *(u32*)(outh + base) = hp;
                    *(u32*)(outl + base) = lp;
                } else {
                    *(float2*)(outf + base) = make_float2(v0, v1);
                }
            }
        }
        // ---- commit prefetched row into ring slot ----
        __syncthreads();
        {
            u32 base = Aoff + (u32)((g2 + 3) % 3)*ASLOT;
            #pragma unroll
            for (int i = 0; i < 8; ++i) {
                int c = tid + i*256;
                int plane = c >> 10, rem = c & 1023, px = rem >> 3, q = rem & 7;
                *(uint4*)(dsm + (base - sb) + (u32)plane*APLANE + (u32)(px+1)*AROW + (u32)q*16u) = pf[i];
            }
        }
        __syncthreads();
    }
}

// ---------------------------------------------------------------------------
extern "C" void kernel_launch(void* const* d_in, const int* in_sizes, int n_in,
                              void* d_out, int out_size)
{
    const float* means = (const float*)d_in[0];
    const float* gsf   = (const float*)d_in[2];
    const float* intr  = (const float*)d_in[3];
    const float* extr  = (const float*)d_in[4];
    const float* w1    = (const float*)d_in[5];
    const float* b1    = (const float*)d_in[6];
    const float* w2    = (const float*)d_in[7];
    const float* b2    = (const float*)d_in[8];
    float* out = (float*)d_out;

    __nv_bfloat16 *pfh, *pfl, *pmh, *pml, *pwh, *pwl;
    cudaGetSymbolAddress((void**)&pfh, g_fh);
    cudaGetSymbolAddress((void**)&pfl, g_fl);
    cudaGetSymbolAddress((void**)&pmh, g_mh);
    cudaGetSymbolAddress((void**)&pml, g_ml);
    cudaGetSymbolAddress((void**)&pwh, g_wh);
    cudaGetSymbolAddress((void**)&pwl, g_wl);

    cudaFuncSetAttribute(k_conv_mma<true>,  cudaFuncAttributeMaxDynamicSharedMemorySize, SMEM_REQ);
    cudaFuncSetAttribute(k_conv_mma<false>, cudaFuncAttributeMaxDynamicSharedMemorySize, SMEM_REQ);

    k_prep<<<1, 32>>>(intr, extr);
    k_count<<<NBJ, 256>>>(means);
    k_wsplit<<<288, 256>>>(w1, w2);
    k_fuse2<<<dim3(128, 32), 256>>>(gsf);
    k_conv_mma<true ><<<dim3(2, 2, 32), 256, SMEM_REQ>>>(pfh, pfl, b1, pmh, pml, nullptr, pwh, pwl);
    k_conv_mma<false><<<dim3(2, 2, 32), 256, SMEM_REQ>>>(pmh, pml, b2, nullptr, nullptr, out,
                                                         pwh + 9*64*64, pwl + 9*64*64);
}

// round 9
// speedup vs baseline: 4.9269x; 1.4039x over previous
#include <cuda_runtime.h>
#include <cuda_fp16.h>
#include <math.h>
#include <stdint.h>

#define Bv 4
#define Vv 8
#define HW 16384
#define VP 7
#define NBJ 28
#define NIMG 32
typedef unsigned long long u64;
typedef uint32_t u32;

// ------------------------- device scratch -------------------------
__device__ __half g_fh[NIMG*HW*64];
__device__ __half g_fl[NIMG*HW*64];
__device__ __half g_mh[NIMG*HW*64];
__device__ __half g_ml[NIMG*HW*64];
__device__ __half g_wh[2*9*64*64];   // [layer][tap][ic][oc]
__device__ __half g_wl[2*9*64*64];
__device__ int   g_src[NBJ*HW];
__device__ float g_wgt[NBJ];
__device__ float g_cam[NBJ*24];

// ------------------------- PTX helpers -------------------------
__device__ __forceinline__ u32 s2u(const void* p) {
    u32 a;
    asm("{ .reg .u64 t; cvta.to.shared.u64 t, %1; cvt.u32.u64 %0, t; }" : "=r"(a) : "l"(p));
    return a;
}
__device__ __forceinline__ void ldsm4(u32* r, u32 addr) {
    asm volatile("ldmatrix.sync.aligned.m8n8.x4.shared.b16 {%0,%1,%2,%3}, [%4];"
        : "=r"(r[0]), "=r"(r[1]), "=r"(r[2]), "=r"(r[3]) : "r"(addr));
}
__device__ __forceinline__ void ldsm4t(u32* r, u32 addr) {
    asm volatile("ldmatrix.sync.aligned.m8n8.x4.trans.shared.b16 {%0,%1,%2,%3}, [%4];"
        : "=r"(r[0]), "=r"(r[1]), "=r"(r[2]), "=r"(r[3]) : "r"(addr));
}
__device__ __forceinline__ void mma_fp16(float* d, const u32* a, const u32* b) {
    asm volatile("mma.sync.aligned.m16n8k16.row.col.f32.f16.f16.f32 "
        "{%0,%1,%2,%3}, {%4,%5,%6,%7}, {%8,%9}, {%0,%1,%2,%3};"
        : "+f"(d[0]), "+f"(d[1]), "+f"(d[2]), "+f"(d[3])
        : "r"(a[0]), "r"(a[1]), "r"(a[2]), "r"(a[3]), "r"(b[0]), "r"(b[1]));
}

// ---------------------------------------------------------------------------
// Kernel 1: camera precompute (proven — exact JAX mirror)
// ---------------------------------------------------------------------------
__global__ void k_prep(const float* __restrict__ intr, const float* __restrict__ extr)
{
    int t = threadIdx.x;
    if (t >= NBJ) return;
    int b = t / VP, j = t % VP, k = j + 1;
    const float* E = extr + (b*Vv + k)*16;
    const float* K = intr + (b*Vv + k)*9;
    float m[16], inv[16];
    #pragma unroll
    for (int i = 0; i < 16; ++i) m[i] = E[i];

    inv[0]  =  m[5]*m[10]*m[15] - m[5]*m[11]*m[14] - m[9]*m[6]*m[15] + m[9]*m[7]*m[14] + m[13]*m[6]*m[11] - m[13]*m[7]*m[10];
    inv[4]  = -m[4]*m[10]*m[15] + m[4]*m[11]*m[14] + m[8]*m[6]*m[15] - m[8]*m[7]*m[14] - m[12]*m[6]*m[11] + m[12]*m[7]*m[10];
    inv[8]  =  m[4]*m[9]*m[15]  - m[4]*m[11]*m[13] - m[8]*m[5]*m[15] + m[8]*m[7]*m[13] + m[12]*m[5]*m[11] - m[12]*m[7]*m[9];
    inv[12] = -m[4]*m[9]*m[14]  + m[4]*m[10]*m[13] + m[8]*m[5]*m[14] - m[8]*m[6]*m[13] - m[12]*m[5]*m[10] + m[12]*m[6]*m[9];
    inv[1]  = -m[1]*m[10]*m[15] + m[1]*m[11]*m[14] + m[9]*m[2]*m[15] - m[9]*m[3]*m[14] - m[13]*m[2]*m[11] + m[13]*m[3]*m[10];
    inv[5]  =  m[0]*m[10]*m[15] - m[0]*m[11]*m[14] - m[8]*m[2]*m[15] + m[8]*m[3]*m[14] + m[12]*m[2]*m[11] - m[12]*m[3]*m[10];
    inv[9]  = -m[0]*m[9]*m[15]  + m[0]*m[11]*m[13] + m[8]*m[1]*m[15] - m[8]*m[3]*m[13] - m[12]*m[1]*m[11] + m[12]*m[3]*m[9];
    inv[13] =  m[0]*m[9]*m[14]  - m[0]*m[10]*m[13] - m[8]*m[1]*m[14] + m[8]*m[2]*m[13] + m[12]*m[1]*m[10] - m[12]*m[2]*m[9];
    inv[2]  =  m[1]*m[6]*m[15]  - m[1]*m[7]*m[14]  - m[5]*m[2]*m[15] + m[5]*m[3]*m[14] + m[13]*m[2]*m[7]  - m[13]*m[3]*m[6];
    inv[6]  = -m[0]*m[6]*m[15]  + m[0]*m[7]*m[14]  + m[4]*m[2]*m[15] - m[4]*m[3]*m[14] - m[12]*m[2]*m[7]  + m[12]*m[3]*m[6];
    inv[10] =  m[0]*m[5]*m[15]  - m[0]*m[7]*m[13]  - m[4]*m[1]*m[15] + m[4]*m[3]*m[13] + m[12]*m[1]*m[7]  - m[12]*m[3]*m[5];
    inv[14] = -m[0]*m[5]*m[14]  + m[0]*m[6]*m[13]  + m[4]*m[1]*m[14] - m[4]*m[2]*m[13] - m[12]*m[1]*m[6]  + m[12]*m[2]*m[5];
    inv[3]  = -m[1]*m[6]*m[11]  + m[1]*m[7]*m[10]  + m[5]*m[2]*m[11] - m[5]*m[3]*m[10] - m[9]*m[2]*m[7]   + m[9]*m[3]*m[6];
    inv[7]  =  m[0]*m[6]*m[11]  - m[0]*m[7]*m[10]  - m[4]*m[2]*m[11] + m[4]*m[3]*m[10] + m[8]*m[2]*m[7]   - m[8]*m[3]*m[6];
    inv[11] = -m[0]*m[5]*m[11]  + m[0]*m[7]*m[9]   + m[4]*m[1]*m[11] - m[4]*m[3]*m[9]  - m[8]*m[1]*m[7]   + m[8]*m[3]*m[5];
    inv[15] =  m[0]*m[5]*m[10]  - m[0]*m[6]*m[9]   - m[4]*m[1]*m[10] + m[4]*m[2]*m[9]  + m[8]*m[1]*m[6]   - m[8]*m[2]*m[5];

    float det = m[0]*inv[0] + m[1]*inv[4] + m[2]*inv[8] + m[3]*inv[12];
    float id = 1.0f / det;
    #pragma unroll
    for (int i = 0; i < 16; ++i) inv[i] *= id;

    float* o = g_cam + t*24;
    #pragma unroll
    for (int i = 0; i < 12; ++i) o[i] = inv[i];
    #pragma unroll
    for (int i = 0; i < 9; ++i) o[12 + i] = K[i];
}

// ---------------------------------------------------------------------------
// Kernel 2: projection -> gather index + count (proven)
// ---------------------------------------------------------------------------
__global__ void k_count(const float* __restrict__ means)
{
    int bj = blockIdx.x;
    int b = bj / VP, j = bj % VP;
    __shared__ float cm[24];
    __shared__ int s_cnt;
    if (threadIdx.x < 24) cm[threadIdx.x] = g_cam[bj*24 + threadIdx.x];
    if (threadIdx.x == 0) s_cnt = 0;
    __syncthreads();
    const float* mb = means + (size_t)(b*Vv + j)*HW*3;
    int cnt = 0;
    for (int i = threadIdx.x; i < HW; i += blockDim.x) {
        float x = mb[i*3+0], y = mb[i*3+1], z = mb[i*3+2];
        float c0 = __fadd_rn(__fadd_rn(__fadd_rn(__fmul_rn(cm[0],x), __fmul_rn(cm[1],y)), __fmul_rn(cm[2],z)), cm[3]);
        float c1 = __fadd_rn(__fadd_rn(__fadd_rn(__fmul_rn(cm[4],x), __fmul_rn(cm[5],y)), __fmul_rn(cm[6],z)), cm[7]);
        float c2 = __fadd_rn(__fadd_rn(__fadd_rn(__fmul_rn(cm[8],x), __fmul_rn(cm[9],y)), __fmul_rn(cm[10],z)), cm[11]);
        float p0 = __fadd_rn(__fadd_rn(__fmul_rn(cm[12],c0), __fmul_rn(cm[13],c1)), __fmul_rn(cm[14],c2));
        float p1 = __fadd_rn(__fadd_rn(__fmul_rn(cm[15],c0), __fmul_rn(cm[16],c1)), __fmul_rn(cm[17],c2));
        float p2 = __fadd_rn(__fadd_rn(__fmul_rn(cm[18],c0), __fmul_rn(cm[19],c1)), __fmul_rn(cm[20],c2));
        float d  = __fadd_rn(p2, 1e-8f);
        float nx = p0 / d, ny = p1 / d;
        bool valid = (nx >= 0.f) && (nx < 1.f) && (ny >= 0.f) && (ny < 1.f) && (c2 > 1e-8f);
        int px = (int)floorf(__fmul_rn(nx, 128.f)); px = min(max(px, 0), 127);
        int py = (int)floorf(__fmul_rn(ny, 128.f)); py = min(max(py, 0), 127);
        g_src[bj*HW + i] = valid ? (py*128 + px) : -1;
        cnt += valid ? 1 : 0;
    }
    atomicAdd(&s_cnt, cnt);
    __syncthreads();
    if (threadIdx.x == 0) g_wgt[bj] = (0.1f / (float)HW) * (float)s_cnt;
}

// ---------------------------------------------------------------------------
// Kernel 3: weight split fp32 -> fp16 hi/lo, layout [layer][tap][ic][oc]
// ---------------------------------------------------------------------------
__global__ void k_wsplit(const float* __restrict__ w1, const float* __restrict__ w2)
{
    int idx = blockIdx.x*256 + threadIdx.x;
    if (idx >= 2*9*64*64) return;
    int layer = idx / 36864; int rem = idx - layer*36864;
    int tap = rem >> 12;
    int ic = (rem >> 6) & 63, oc = rem & 63;
    const float* w = layer ? w2 : w1;
    float v = w[(oc*64 + ic)*9 + tap];
    __half h = __float2half(v);
    g_wh[idx] = h;
    g_wl[idx] = __float2half(v - __half2float(h));
}

// ---------------------------------------------------------------------------
// Kernel 4: fuse -> NHWC fp16 hi/lo planes
// ---------------------------------------------------------------------------
__global__ __launch_bounds__(256)
void k_fuse2(const float* __restrict__ gsf)
{
    int y = blockIdx.x, n = blockIdx.y;
    int b = n >> 3, view = n & 7;
    __shared__ int S[128];
    __shared__ float s_w;
    int tid = threadIdx.x;
    if (view < VP) {
        int bj = b*VP + view;
        if (tid < 128) S[tid] = g_src[bj*HW + y*128 + tid];
        if (tid == 0) s_w = g_wgt[bj];
    } else {
        if (tid < 128) S[tid] = -1;
        if (tid == 0) s_w = 0.f;
    }
    __syncthreads();
    float wg = s_w, iw = 1.f / (1.f + wg);
    const float* fj = gsf + ((size_t)n*HW + (size_t)y*128)*64;
    const float* fk = gsf + (size_t)(n+1)*HW*64;
    size_t ob = ((size_t)n*HW + (size_t)y*128)*64;
    #pragma unroll
    for (int i = 0; i < 8; ++i) {
        int idx = tid + i*256;
        int px = idx >> 4, c4 = (idx & 15)*4;
        float4 a = *(const float4*)(fj + px*64 + c4);
        int s = S[px];
        float4 g = make_float4(0.f,0.f,0.f,0.f);
        if (s >= 0) g = *(const float4*)(fk + (size_t)s*64 + c4);
        float v0 = (a.x + g.x*wg)*iw, v1 = (a.y + g.y*wg)*iw;
        float v2 = (a.z + g.z*wg)*iw, v3 = (a.w + g.w*wg)*iw;
        __half h0 = __float2half(v0), h1 = __float2half(v1);
        __half h2 = __float2half(v2), h3 = __float2half(v3);
        __half l0 = __float2half(v0 - __half2float(h0));
        __half l1 = __float2half(v1 - __half2float(h1));
        __half l2 = __float2half(v2 - __half2float(h2));
        __half l3 = __float2half(v3 - __half2float(h3));
        uint2 ph, pl;
        ph.x = (u32)__half_as_ushort(h0) | ((u32)__half_as_ushort(h1) << 16);
        ph.y = (u32)__half_as_ushort(h2) | ((u32)__half_as_ushort(h3) << 16);
        pl.x = (u32)__half_as_ushort(l0) | ((u32)__half_as_ushort(l1) << 16);
        pl.y = (u32)__half_as_ushort(l2) | ((u32)__half_as_ushort(l3) << 16);
        *(uint2*)(g_fh + ob + px*64 + c4) = ph;
        *(uint2*)(g_fl + ob + px*64 + c4) = pl;
    }
}

// ---------------------------------------------------------------------------
// Kernel 5/6: mma.sync fp16 2-term split conv. grid(2 ochalf, 2 slab, 32 img),
// 256 threads = 8 warps, warp tile 16px x 32oc.
// SMEM: B 9 tiles [64ic x 32oc] stride 80B = 46080B;
//       A ring 3 slots x 2 planes x [130 rows x 64ic] stride 144B = 112320B.
// ---------------------------------------------------------------------------
#define BTILE 5120u
#define AROW 144u
#define APLANE 18720u
#define ASLOT 37440u
#define BOFF_SZ 46080u
#define SMEM_REQ 158400

template<bool FIRST>
__global__ void __launch_bounds__(256, 1) k_conv_mma(
    const __half* __restrict__ inh, const __half* __restrict__ inl,
    const float* __restrict__ bias,
    __half* __restrict__ outh, __half* __restrict__ outl,
    float* __restrict__ outf,
    const __half* __restrict__ wh, const __half* __restrict__ wl)
{
    extern __shared__ char dsm[];
    u32 sb = s2u(dsm);
    u32 Boff = sb, Aoff = sb + BOFF_SZ;

    int ochalf = blockIdx.x, slab = blockIdx.y, n = blockIdx.z;
    int oc0 = ochalf*32, ybase = slab*64;
    int tid = threadIdx.x, wid = tid >> 5, t = tid & 31;
    int px0 = wid*16;
    (void)wl;

    // ---- B build: 9 (tap) hi tiles, stride-80 rows ----
    #pragma unroll
    for (int i = 0; i < 9; ++i) {
        int c = tid + i*256;              // 2304 chunks of 16B
        int tap = c >> 8;
        int rem = c & 255;
        int ic = rem >> 2, q = rem & 3;
        uint4 v = *(const uint4*)(wh + ((size_t)tap*64 + ic)*64 + oc0 + q*8);
        *(uint4*)(dsm + (u32)tap*BTILE + (u32)ic*80u + (u32)q*16u) = v;
    }
    // ---- zero halo rows 0 and 129 of all 3 slots x 2 planes ----
    if (tid < 96) {
        int slot = tid / 32, rem = tid & 31;
        int plane = rem >> 4, rr = (rem >> 3) & 1, q = rem & 7;
        u32 off = BOFF_SZ + (u32)slot*ASLOT + (u32)plane*APLANE + (rr ? 129u*AROW : 0u) + (u32)q*16u;
        *(uint4*)(dsm + off) = make_uint4(0,0,0,0);
    }
    // ---- prologue: build rows ybase-1 .. ybase+1 ----
    for (int r = ybase-1; r <= ybase+1; ++r) {
        int slot = (r + 3) % 3;
        u32 base = BOFF_SZ + (u32)slot*ASLOT;
        bool vr = ((unsigned)r < 128u);
        #pragma unroll
        for (int i = 0; i < 8; ++i) {
            int c = tid + i*256;          // 2048 chunks
            int plane = c >> 10, rem = c & 1023, px = rem >> 3, q = rem & 7;
            uint4 v = make_uint4(0,0,0,0);
            if (vr) v = *(const uint4*)((plane ? inl : inh) + ((size_t)n*HW + (size_t)r*128 + px)*64 + q*8);
            *(uint4*)(dsm + base + (u32)plane*APLANE + (u32)(px+1)*AROW + (u32)q*16u) = v;
        }
    }
    // per-thread bias regs
    float bo0[4], bo1[4];
    #pragma unroll
    for (int nb = 0; nb < 4; ++nb) {
        int oc = oc0 + nb*8 + (t & 3)*2;
        bo0[nb] = bias[oc];
        bo1[nb] = bias[oc + 1];
    }
    __syncthreads();

    u32 laneA = (u32)(t & 15)*AROW + (u32)((t >> 4) << 4);
    u32 laneB = (u32)(t & 15)*80u  + (u32)((t >> 4) << 4);

    for (int y = 0; y < 64; ++y) {
        int gy = ybase + y;
        // ---- prefetch row gy+2 into regs ----
        uint4 pf[8];
        int g2 = gy + 2;
        bool v2 = (g2 <= 127);
        #pragma unroll
        for (int i = 0; i < 8; ++i) {
            int c = tid + i*256;
            int plane = c >> 10, rem = c & 1023, px = rem >> 3, q = rem & 7;
            pf[i] = make_uint4(0,0,0,0);
            if (v2) pf[i] = *(const uint4*)((plane ? inl : inh) + ((size_t)n*HW + (size_t)g2*128 + px)*64 + q*8);
        }
        // ---- k-loop ----
        float acc[4][4];
        #pragma unroll
        for (int nb = 0; nb < 4; ++nb)
            #pragma unroll
            for (int i = 0; i < 4; ++i) acc[nb][i] = 0.f;

        u32 aH[3];
        #pragma unroll
        for (int dy = 0; dy < 3; ++dy) {
            int r = gy - 1 + dy;
            aH[dy] = Aoff + (u32)((r + 3) % 3)*ASLOT;
        }
        #pragma unroll 1
        for (int dy = 0; dy < 3; ++dy) {
            #pragma unroll
            for (int dx = 0; dx < 3; ++dx) {
                u32 rowoff = (u32)(px0 + dx)*AROW + laneA;
                u32 ah = aH[dy] + rowoff;
                u32 al = ah + APLANE;
                u32 bb = Boff + (u32)(dy*3 + dx)*BTILE + laneB;
                #pragma unroll
                for (int kc = 0; kc < 4; ++kc) {
                    u32 Ah[4], Al[4], Bh[8];
                    ldsm4(Ah, ah + kc*32);
                    ldsm4(Al, al + kc*32);
                    ldsm4t(Bh,     bb + kc*1280u);
                    ldsm4t(Bh + 4, bb + kc*1280u + 32u);
                    #pragma unroll
                    for (int nb = 0; nb < 4; ++nb) {
                        mma_fp16(acc[nb], Ah, &Bh[nb*2]);
                        mma_fp16(acc[nb], Al, &Bh[nb*2]);
                    }
                }
            }
        }
        // ---- epilogue: bias (+gelu), store row gy ----
        #pragma unroll
        for (int nb = 0; nb < 4; ++nb) {
            int oc = oc0 + nb*8 + (t & 3)*2;
            #pragma unroll
            for (int rg = 0; rg < 2; ++rg) {
                int px = px0 + (t >> 2) + rg*8;
                float v0 = acc[nb][rg*2]   + bo0[nb];
                float v1 = acc[nb][rg*2+1] + bo1[nb];
                size_t base = ((size_t)n*HW + (size_t)gy*128 + px)*64 + oc;
                if (FIRST) {
                    v0 = 0.5f * v0 * (1.0f + erff(v0 * 0.70710678118654752f));
                    v1 = 0.5f * v1 * (1.0f + erff(v1 * 0.70710678118654752f));
                    __half h0 = __float2half(v0);
                    __half h1 = __float2half(v1);
                    __half l0 = __float2half(v0 - __half2float(h0));
                    __half l1 = __float2half(v1 - __half2float(h1));
                    u32 hp = (u32)__half_as_ushort(h0) | ((u32)__half_as_ushort(h1) << 16);
                    u32 lp = (u32)__half_as_ushort(l0) | ((u32)__half_as_ushort(l1) << 16);
                    *(u32*)(outh + base) = hp;
                    *(u32*)(outl + base) = lp;
                } else {
                    *(float2*)(outf + base) = make_float2(v0, v1);
                }
            }
        }
        // ---- commit prefetched row into ring slot ----
        __syncthreads();
        {
            u32 base = Aoff + (u32)((g2 + 3) % 3)*ASLOT;
            #pragma unroll
            for (int i = 0; i < 8; ++i) {
                int c = tid + i*256;
                int plane = c >> 10, rem = c & 1023, px = rem >> 3, q = rem & 7;
                *(uint4*)(dsm + (base - sb) + (u32)plane*APLANE + (u32)(px+1)*AROW + (u32)q*16u) = pf[i];
            }
        }
        __syncthreads();
    }
}

// ---------------------------------------------------------------------------
extern "C" void kernel_launch(void* const* d_in, const int* in_sizes, int n_in,
                              void* d_out, int out_size)
{
    const float* means = (const float*)d_in[0];
    const float* gsf   = (const float*)d_in[2];
    const float* intr  = (const float*)d_in[3];
    const float* extr  = (const float*)d_in[4];
    const float* w1    = (const float*)d_in[5];
    const float* b1    = (const float*)d_in[6];
    const float* w2    = (const float*)d_in[7];
    const float* b2    = (const float*)d_in[8];
    float* out = (float*)d_out;

    __half *pfh, *pfl, *pmh, *pml, *pwh, *pwl;
    cudaGetSymbolAddress((void**)&pfh, g_fh);
    cudaGetSymbolAddress((void**)&pfl, g_fl);
    cudaGetSymbolAddress((void**)&pmh, g_mh);
    cudaGetSymbolAddress((void**)&pml, g_ml);
    cudaGetSymbolAddress((void**)&pwh, g_wh);
    cudaGetSymbolAddress((void**)&pwl, g_wl);

    cudaFuncSetAttribute(k_conv_mma<true>,  cudaFuncAttributeMaxDynamicSharedMemorySize, SMEM_REQ);
    cudaFuncSetAttribute(k_conv_mma<false>, cudaFuncAttributeMaxDynamicSharedMemorySize, SMEM_REQ);

    k_prep<<<1, 32>>>(intr, extr);
    k_count<<<NBJ, 256>>>(means);
    k_wsplit<<<288, 256>>>(w1, w2);
    k_fuse2<<<dim3(128, 32), 256>>>(gsf);
    k_conv_mma<true ><<<dim3(2, 2, 32), 256, SMEM_REQ>>>(pfh, pfl, b1, pmh, pml, nullptr, pwh, pwl);
    k_conv_mma<false><<<dim3(2, 2, 32), 256, SMEM_REQ>>>(pmh, pml, b2, nullptr, nullptr, out,
                                                         pwh + 9*64*64, pwl + 9*64*64);
}

// round 10
// speedup vs baseline: 8.7372x; 1.7734x over previous
#include <cuda_runtime.h>
#include <cuda_fp16.h>
#include <math.h>
#include <stdint.h>

#define Bv 4
#define Vv 8
#define HW 16384
#define VP 7
#define NBJ 28
#define NIMG 32
typedef unsigned long long u64;
typedef uint32_t u32;

// ------------------------- device scratch -------------------------
__device__ __half g_fh[NIMG*HW*64];   // fused features fp16, NHWC
__device__ __half g_mh[NIMG*HW*64];   // gelu(conv1) fp16, NHWC
__device__ __half g_wh[2*9*64*64];    // [layer][tap][ic][oc] fp16
__device__ int   g_src[NBJ*HW];
__device__ int   g_cnt[NBJ];
__device__ float g_cam[NBJ*24];

// ------------------------- PTX helpers -------------------------
__device__ __forceinline__ u32 s2u(const void* p) {
    u32 a;
    asm("{ .reg .u64 t; cvta.to.shared.u64 t, %1; cvt.u32.u64 %0, t; }" : "=r"(a) : "l"(p));
    return a;
}
__device__ __forceinline__ void ldsm4(u32* r, u32 addr) {
    asm volatile("ldmatrix.sync.aligned.m8n8.x4.shared.b16 {%0,%1,%2,%3}, [%4];"
        : "=r"(r[0]), "=r"(r[1]), "=r"(r[2]), "=r"(r[3]) : "r"(addr));
}
__device__ __forceinline__ void ldsm4t(u32* r, u32 addr) {
    asm volatile("ldmatrix.sync.aligned.m8n8.x4.trans.shared.b16 {%0,%1,%2,%3}, [%4];"
        : "=r"(r[0]), "=r"(r[1]), "=r"(r[2]), "=r"(r[3]) : "r"(addr));
}
__device__ __forceinline__ void mma_fp16(float* d, const u32* a, const u32* b) {
    asm volatile("mma.sync.aligned.m16n8k16.row.col.f32.f16.f16.f32 "
        "{%0,%1,%2,%3}, {%4,%5,%6,%7}, {%8,%9}, {%0,%1,%2,%3};"
        : "+f"(d[0]), "+f"(d[1]), "+f"(d[2]), "+f"(d[3])
        : "r"(a[0]), "r"(a[1]), "r"(a[2]), "r"(a[3]), "r"(b[0]), "r"(b[1]));
}

// ---------------------------------------------------------------------------
// Kernel 1: camera precompute (proven — exact JAX mirror) + zero g_cnt
// ---------------------------------------------------------------------------
__global__ void k_prep(const float* __restrict__ intr, const float* __restrict__ extr)
{
    int t = threadIdx.x;
    if (t < NBJ) g_cnt[t] = 0;
    if (t >= NBJ) return;
    int b = t / VP, j = t % VP, k = j + 1;
    const float* E = extr + (b*Vv + k)*16;
    const float* K = intr + (b*Vv + k)*9;
    float m[16], inv[16];
    #pragma unroll
    for (int i = 0; i < 16; ++i) m[i] = E[i];

    inv[0]  =  m[5]*m[10]*m[15] - m[5]*m[11]*m[14] - m[9]*m[6]*m[15] + m[9]*m[7]*m[14] + m[13]*m[6]*m[11] - m[13]*m[7]*m[10];
    inv[4]  = -m[4]*m[10]*m[15] + m[4]*m[11]*m[14] + m[8]*m[6]*m[15] - m[8]*m[7]*m[14] - m[12]*m[6]*m[11] + m[12]*m[7]*m[10];
    inv[8]  =  m[4]*m[9]*m[15]  - m[4]*m[11]*m[13] - m[8]*m[5]*m[15] + m[8]*m[7]*m[13] + m[12]*m[5]*m[11] - m[12]*m[7]*m[9];
    inv[12] = -m[4]*m[9]*m[14]  + m[4]*m[10]*m[13] + m[8]*m[5]*m[14] - m[8]*m[6]*m[13] - m[12]*m[5]*m[10] + m[12]*m[6]*m[9];
    inv[1]  = -m[1]*m[10]*m[15] + m[1]*m[11]*m[14] + m[9]*m[2]*m[15] - m[9]*m[3]*m[14] - m[13]*m[2]*m[11] + m[13]*m[3]*m[10];
    inv[5]  =  m[0]*m[10]*m[15] - m[0]*m[11]*m[14] - m[8]*m[2]*m[15] + m[8]*m[3]*m[14] + m[12]*m[2]*m[11] - m[12]*m[3]*m[10];
    inv[9]  = -m[0]*m[9]*m[15]  + m[0]*m[11]*m[13] + m[8]*m[1]*m[15] - m[8]*m[3]*m[13] - m[12]*m[1]*m[11] + m[12]*m[3]*m[9];
    inv[13] =  m[0]*m[9]*m[14]  - m[0]*m[10]*m[13] - m[8]*m[1]*m[14] + m[8]*m[2]*m[13] + m[12]*m[1]*m[10] - m[12]*m[2]*m[9];
    inv[2]  =  m[1]*m[6]*m[15]  - m[1]*m[7]*m[14]  - m[5]*m[2]*m[15] + m[5]*m[3]*m[14] + m[13]*m[2]*m[7]  - m[13]*m[3]*m[6];
    inv[6]  = -m[0]*m[6]*m[15]  + m[0]*m[7]*m[14]  + m[4]*m[2]*m[15] - m[4]*m[3]*m[14] - m[12]*m[2]*m[7]  + m[12]*m[3]*m[6];
    inv[10] =  m[0]*m[5]*m[15]  - m[0]*m[7]*m[13]  - m[4]*m[1]*m[15] + m[4]*m[3]*m[13] + m[12]*m[1]*m[7]  - m[12]*m[3]*m[5];
    inv[14] = -m[0]*m[5]*m[14]  + m[0]*m[6]*m[13]  + m[4]*m[1]*m[14] - m[4]*m[2]*m[13] - m[12]*m[1]*m[6]  + m[12]*m[2]*m[5];
    inv[3]  = -m[1]*m[6]*m[11]  + m[1]*m[7]*m[10]  + m[5]*m[2]*m[11] - m[5]*m[3]*m[10] - m[9]*m[2]*m[7]   + m[9]*m[3]*m[6];
    inv[7]  =  m[0]*m[6]*m[11]  - m[0]*m[7]*m[10]  - m[4]*m[2]*m[11] + m[4]*m[3]*m[10] + m[8]*m[2]*m[7]   - m[8]*m[3]*m[6];
    inv[11] = -m[0]*m[5]*m[11]  + m[0]*m[7]*m[9]   + m[4]*m[1]*m[11] - m[4]*m[3]*m[9]  - m[8]*m[1]*m[7]   + m[8]*m[3]*m[5];
    inv[15] =  m[0]*m[5]*m[10]  - m[0]*m[6]*m[9]   - m[4]*m[1]*m[10] + m[4]*m[2]*m[9]  + m[8]*m[1]*m[6]   - m[8]*m[2]*m[5];

    float det = m[0]*inv[0] + m[1]*inv[4] + m[2]*inv[8] + m[3]*inv[12];
    float id = 1.0f / det;
    #pragma unroll
    for (int i = 0; i < 16; ++i) inv[i] *= id;

    float* o = g_cam + t*24;
    #pragma unroll
    for (int i = 0; i < 12; ++i) o[i] = inv[i];
    #pragma unroll
    for (int i = 0; i < 9; ++i) o[12 + i] = K[i];
}

// ---------------------------------------------------------------------------
// Kernel 2: projection -> gather index + count (proven math, 4-way split)
// ---------------------------------------------------------------------------
__global__ void k_count(const float* __restrict__ means)
{
    int bj = blockIdx.x;
    int b = bj / VP, j = bj % VP;
    __shared__ float cm[24];
    __shared__ int s_cnt;
    if (threadIdx.x < 24) cm[threadIdx.x] = g_cam[bj*24 + threadIdx.x];
    if (threadIdx.x == 0) s_cnt = 0;
    __syncthreads();
    const float* mb = means + (size_t)(b*Vv + j)*HW*3;
    int cnt = 0;
    int i0 = blockIdx.y * 4096;
    for (int i = i0 + threadIdx.x; i < i0 + 4096; i += blockDim.x) {
        float x = mb[i*3+0], y = mb[i*3+1], z = mb[i*3+2];
        float c0 = __fadd_rn(__fadd_rn(__fadd_rn(__fmul_rn(cm[0],x), __fmul_rn(cm[1],y)), __fmul_rn(cm[2],z)), cm[3]);
        float c1 = __fadd_rn(__fadd_rn(__fadd_rn(__fmul_rn(cm[4],x), __fmul_rn(cm[5],y)), __fmul_rn(cm[6],z)), cm[7]);
        float c2 = __fadd_rn(__fadd_rn(__fadd_rn(__fmul_rn(cm[8],x), __fmul_rn(cm[9],y)), __fmul_rn(cm[10],z)), cm[11]);
        float p0 = __fadd_rn(__fadd_rn(__fmul_rn(cm[12],c0), __fmul_rn(cm[13],c1)), __fmul_rn(cm[14],c2));
        float p1 = __fadd_rn(__fadd_rn(__fmul_rn(cm[15],c0), __fmul_rn(cm[16],c1)), __fmul_rn(cm[17],c2));
        float p2 = __fadd_rn(__fadd_rn(__fmul_rn(cm[18],c0), __fmul_rn(cm[19],c1)), __fmul_rn(cm[20],c2));
        float d  = __fadd_rn(p2, 1e-8f);
        float nx = p0 / d, ny = p1 / d;
        bool valid = (nx >= 0.f) && (nx < 1.f) && (ny >= 0.f) && (ny < 1.f) && (c2 > 1e-8f);
        int px = (int)floorf(__fmul_rn(nx, 128.f)); px = min(max(px, 0), 127);
        int py = (int)floorf(__fmul_rn(ny, 128.f)); py = min(max(py, 0), 127);
        g_src[bj*HW + i] = valid ? (py*128 + px) : -1;
        cnt += valid ? 1 : 0;
    }
    atomicAdd(&s_cnt, cnt);
    __syncthreads();
    if (threadIdx.x == 0) atomicAdd(&g_cnt[bj], s_cnt);
}

// ---------------------------------------------------------------------------
// Kernel 3: weight fp32 -> fp16, layout [layer][tap][ic][oc]
// ---------------------------------------------------------------------------
__global__ void k_wsplit(const float* __restrict__ w1, const float* __restrict__ w2)
{
    int idx = blockIdx.x*256 + threadIdx.x;
    if (idx >= 2*9*64*64) return;
    int layer = idx / 36864; int rem = idx - layer*36864;
    int tap = rem >> 12;
    int ic = (rem >> 6) & 63, oc = rem & 63;
    const float* w = layer ? w2 : w1;
    g_wh[idx] = __float2half(w[(oc*64 + ic)*9 + tap]);
}

// ---------------------------------------------------------------------------
// Kernel 4: fuse -> NHWC fp16
// ---------------------------------------------------------------------------
__global__ __launch_bounds__(256)
void k_fuse2(const float* __restrict__ gsf)
{
    int y = blockIdx.x, n = blockIdx.y;
    int b = n >> 3, view = n & 7;
    __shared__ int S[128];
    __shared__ float s_w;
    int tid = threadIdx.x;
    if (view < VP) {
        int bj = b*VP + view;
        if (tid < 128) S[tid] = g_src[bj*HW + y*128 + tid];
        if (tid == 0) s_w = (0.1f / (float)HW) * (float)g_cnt[bj];
    } else {
        if (tid < 128) S[tid] = -1;
        if (tid == 0) s_w = 0.f;
    }
    __syncthreads();
    float wg = s_w, iw = 1.f / (1.f + wg);
    const float* fj = gsf + ((size_t)n*HW + (size_t)y*128)*64;
    const float* fk = gsf + (size_t)(n+1)*HW*64;
    size_t ob = ((size_t)n*HW + (size_t)y*128)*64;
    #pragma unroll
    for (int i = 0; i < 8; ++i) {
        int idx = tid + i*256;
        int px = idx >> 4, c4 = (idx & 15)*4;
        float4 a = *(const float4*)(fj + px*64 + c4);
        int s = S[px];
        float4 g = make_float4(0.f,0.f,0.f,0.f);
        if (s >= 0) g = *(const float4*)(fk + (size_t)s*64 + c4);
        float v0 = (a.x + g.x*wg)*iw, v1 = (a.y + g.y*wg)*iw;
        float v2 = (a.z + g.z*wg)*iw, v3 = (a.w + g.w*wg)*iw;
        uint2 ph;
        ph.x = (u32)__half_as_ushort(__float2half(v0)) | ((u32)__half_as_ushort(__float2half(v1)) << 16);
        ph.y = (u32)__half_as_ushort(__float2half(v2)) | ((u32)__half_as_ushort(__float2half(v3)) << 16);
        *(uint2*)(g_fh + ob + px*64 + c4) = ph;
    }
}

// ---------------------------------------------------------------------------
// Kernel 5/6: mma.sync fp16 single-term conv, row-paired.
// grid(2 ochalf, 2 slab, 32 img), 256 threads = 8 warps, warp 16px x 32oc x 2rows.
// SMEM: B 9 tiles [64ic x 32oc] stride 80B = 46080B;
//       A ring 6 slots x [130 rows x 64ic] stride 144B = 112320B.
// ---------------------------------------------------------------------------
#define BTILE 5120u
#define AROW 144u
#define ASLOT 18720u
#define BOFF_SZ 46080u
#define SMEM_REQ 158400

template<bool FIRST>
__global__ void __launch_bounds__(256, 1) k_conv_mma(
    const __half* __restrict__ inh, const float* __restrict__ bias,
    __half* __restrict__ outh, float* __restrict__ outf,
    const __half* __restrict__ wh)
{
    extern __shared__ char dsm[];
    u32 sb = s2u(dsm);
    u32 Boff = sb, Aoff = sb + BOFF_SZ;

    int ochalf = blockIdx.x, slab = blockIdx.y, n = blockIdx.z;
    int oc0 = ochalf*32, ybase = slab*64;
    int tid = threadIdx.x, wid = tid >> 5, t = tid & 31;
    int px0 = wid*16;

    // ---- B build: 9 tap tiles, stride-80 rows ----
    #pragma unroll
    for (int i = 0; i < 9; ++i) {
        int c = tid + i*256;
        int tap = c >> 8;
        int rem = c & 255;
        int ic = rem >> 2, q = rem & 3;
        uint4 v = *(const uint4*)(wh + ((size_t)tap*64 + ic)*64 + oc0 + q*8);
        *(uint4*)(dsm + (u32)tap*BTILE + (u32)ic*80u + (u32)q*16u) = v;
    }
    // ---- zero halo rows 0 and 129 of all 6 slots ----
    if (tid < 108) {
        int slot = tid / 18, rem = tid % 18;
        int rr = rem / 9, q = rem % 9;
        u32 off = BOFF_SZ + (u32)slot*ASLOT + (rr ? 129u*AROW : 0u) + (u32)q*16u;
        *(uint4*)(dsm + off) = make_uint4(0,0,0,0);
    }
    // ---- prologue: build rows ybase-1 .. ybase+2 ----
    for (int r = ybase-1; r <= ybase+2; ++r) {
        int slot = (r + 6) % 6;
        u32 base = BOFF_SZ + (u32)slot*ASLOT;
        bool vr = ((unsigned)r < 128u);
        #pragma unroll
        for (int i = 0; i < 4; ++i) {
            int c = tid + i*256;           // 1024 chunks of 16B
            int px = c >> 3, q = c & 7;
            uint4 v = make_uint4(0,0,0,0);
            if (vr) v = *(const uint4*)(inh + ((size_t)n*HW + (size_t)r*128 + px)*64 + q*8);
            *(uint4*)(dsm + base + (u32)(px+1)*AROW + (u32)q*16u) = v;
        }
    }
    // per-thread bias regs
    float bo0[4], bo1[4];
    #pragma unroll
    for (int nb = 0; nb < 4; ++nb) {
        int oc = oc0 + nb*8 + (t & 3)*2;
        bo0[nb] = bias[oc];
        bo1[nb] = bias[oc + 1];
    }
    __syncthreads();

    u32 laneA = (u32)(t & 15)*AROW + (u32)((t >> 4) << 4);
    u32 laneB = (u32)(t & 15)*80u  + (u32)((t >> 4) << 4);

    #pragma unroll 1
    for (int it = 0; it < 32; ++it) {
        int gy = ybase + it*2;
        // ---- prefetch rows gy+3, gy+4 into regs ----
        uint4 pf[2][4];
        #pragma unroll
        for (int rr = 0; rr < 2; ++rr) {
            int r = gy + 3 + rr;
            bool vr = (r <= 127);
            #pragma unroll
            for (int i = 0; i < 4; ++i) {
                int c = tid + i*256;
                int px = c >> 3, q = c & 7;
                pf[rr][i] = make_uint4(0,0,0,0);
                if (vr) pf[rr][i] = *(const uint4*)(inh + ((size_t)n*HW + (size_t)r*128 + px)*64 + q*8);
            }
        }
        // ---- compute rows gy, gy+1 ----
        float acc[2][4][4];
        #pragma unroll
        for (int r = 0; r < 2; ++r)
            #pragma unroll
            for (int nb = 0; nb < 4; ++nb)
                #pragma unroll
                for (int i = 0; i < 4; ++i) acc[r][nb][i] = 0.f;

        u32 abase[4];
        #pragma unroll
        for (int ar = 0; ar < 4; ++ar)
            abase[ar] = Aoff + (u32)((gy - 1 + ar + 6) % 6)*ASLOT;

        #pragma unroll
        for (int dx = 0; dx < 3; ++dx) {
            #pragma unroll
            for (int kc = 0; kc < 4; ++kc) {
                u32 B[3][8];
                #pragma unroll
                for (int dy = 0; dy < 3; ++dy) {
                    u32 bb = Boff + (u32)(dy*3 + dx)*BTILE + laneB + (u32)kc*1280u;
                    ldsm4t(B[dy],     bb);
                    ldsm4t(B[dy] + 4, bb + 32u);
                }
                #pragma unroll
                for (int ar = 0; ar < 4; ++ar) {
                    u32 Af[4];
                    ldsm4(Af, abase[ar] + (u32)(px0 + dx)*AROW + laneA + (u32)kc*32u);
                    if (ar < 3) {
                        #pragma unroll
                        for (int nb = 0; nb < 4; ++nb)
                            mma_fp16(acc[0][nb], Af, &B[ar][nb*2]);
                    }
                    if (ar > 0) {
                        #pragma unroll
                        for (int nb = 0; nb < 4; ++nb)
                            mma_fp16(acc[1][nb], Af, &B[ar-1][nb*2]);
                    }
                }
            }
        }
        // ---- epilogue: bias (+gelu), store rows gy, gy+1 ----
        #pragma unroll
        for (int r = 0; r < 2; ++r) {
            int gyr = gy + r;
            #pragma unroll
            for (int nb = 0; nb < 4; ++nb) {
                int oc = oc0 + nb*8 + (t & 3)*2;
                #pragma unroll
                for (int rg = 0; rg < 2; ++rg) {
                    int px = px0 + (t >> 2) + rg*8;
                    float v0 = acc[r][nb][rg*2]   + bo0[nb];
                    float v1 = acc[r][nb][rg*2+1] + bo1[nb];
                    size_t base = ((size_t)n*HW + (size_t)gyr*128 + px)*64 + oc;
                    if (FIRST) {
                        v0 = 0.5f * v0 * (1.0f + erff(v0 * 0.70710678118654752f));
                        v1 = 0.5f * v1 * (1.0f + erff(v1 * 0.70710678118654752f));
                        u32 hp = (u32)__half_as_ushort(__float2half(v0))
                               | ((u32)__half_as_ushort(__float2half(v1)) << 16);
                        *(u32*)(outh + base) = hp;
                    } else {
                        *(float2*)(outf + base) = make_float2(v0, v1);
                    }
                }
            }
        }
        // ---- commit prefetched rows into ring slots ----
        __syncthreads();
        #pragma unroll
        for (int rr = 0; rr < 2; ++rr) {
            int r = gy + 3 + rr;
            u32 base = BOFF_SZ + (u32)((r + 6) % 6)*ASLOT;
            #pragma unroll
            for (int i = 0; i < 4; ++i) {
                int c = tid + i*256;
                int px = c >> 3, q = c & 7;
                *(uint4*)(dsm + base + (u32)(px+1)*AROW + (u32)q*16u) = pf[rr][i];
            }
        }
        __syncthreads();
    }
}

// ---------------------------------------------------------------------------
extern "C" void kernel_launch(void* const* d_in, const int* in_sizes, int n_in,
                              void* d_out, int out_size)
{
    const float* means = (const float*)d_in[0];
    const float* gsf   = (const float*)d_in[2];
    const float* intr  = (const float*)d_in[3];
    const float* extr  = (const float*)d_in[4];
    const float* w1    = (const float*)d_in[5];
    const float* b1    = (const float*)d_in[6];
    const float* w2    = (const float*)d_in[7];
    const float* b2    = (const float*)d_in[8];
    float* out = (float*)d_out;

    __half *pfh, *pmh, *pwh;
    cudaGetSymbolAddress((void**)&pfh, g_fh);
    cudaGetSymbolAddress((void**)&pmh, g_mh);
    cudaGetSymbolAddress((void**)&pwh, g_wh);

    cudaFuncSetAttribute(k_conv_mma<true>,  cudaFuncAttributeMaxDynamicSharedMemorySize, SMEM_REQ);
    cudaFuncSetAttribute(k_conv_mma<false>, cudaFuncAttributeMaxDynamicSharedMemorySize, SMEM_REQ);

    k_prep<<<1, 32>>>(intr, extr);
    k_count<<<dim3(NBJ, 4), 256>>>(means);
    k_wsplit<<<288, 256>>>(w1, w2);
    k_fuse2<<<dim3(128, 32), 256>>>(gsf);
    k_conv_mma<true ><<<dim3(2, 2, 32), 256, SMEM_REQ>>>(pfh, b1, pmh, nullptr, pwh);
    k_conv_mma<false><<<dim3(2, 2, 32), 256, SMEM_REQ>>>(pmh, b2, nullptr, out, pwh + 9*64*64);
}

// round 11
// speedup vs baseline: 9.4559x; 1.0823x over previous
#include <cuda_runtime.h>
#include <cuda_fp16.h>
#include <math.h>
#include <stdint.h>

#define Bv 4
#define Vv 8
#define HW 16384
#define VP 7
#define NBJ 28
#define NIMG 32
typedef unsigned long long u64;
typedef uint32_t u32;

// ------------------------- device scratch -------------------------
__device__ __half g_fh[NIMG*HW*64];   // fused features fp16, NHWC
__device__ __half g_mh[NIMG*HW*64];   // gelu(conv1) fp16, NHWC
__device__ __half g_wh[2*9*64*64];    // [layer][tap][ic][oc] fp16
__device__ int   g_src[NBJ*HW];
__device__ int   g_cnt[NBJ];

// ------------------------- PTX helpers -------------------------
__device__ __forceinline__ u32 s2u(const void* p) {
    u32 a;
    asm("{ .reg .u64 t; cvta.to.shared.u64 t, %1; cvt.u32.u64 %0, t; }" : "=r"(a) : "l"(p));
    return a;
}
__device__ __forceinline__ void ldsm4(u32* r, u32 addr) {
    asm volatile("ldmatrix.sync.aligned.m8n8.x4.shared.b16 {%0,%1,%2,%3}, [%4];"
        : "=r"(r[0]), "=r"(r[1]), "=r"(r[2]), "=r"(r[3]) : "r"(addr));
}
__device__ __forceinline__ void ldsm4t(u32* r, u32 addr) {
    asm volatile("ldmatrix.sync.aligned.m8n8.x4.trans.shared.b16 {%0,%1,%2,%3}, [%4];"
        : "=r"(r[0]), "=r"(r[1]), "=r"(r[2]), "=r"(r[3]) : "r"(addr));
}
__device__ __forceinline__ void mma_fp16(float* d, const u32* a, const u32* b) {
    asm volatile("mma.sync.aligned.m16n8k16.row.col.f32.f16.f16.f32 "
        "{%0,%1,%2,%3}, {%4,%5,%6,%7}, {%8,%9}, {%0,%1,%2,%3};"
        : "+f"(d[0]), "+f"(d[1]), "+f"(d[2]), "+f"(d[3])
        : "r"(a[0]), "r"(a[1]), "r"(a[2]), "r"(a[3]), "r"(b[0]), "r"(b[1]));
}
__device__ __forceinline__ void cp_async16(u32 smem, const void* gptr, int szbytes) {
    asm volatile("cp.async.cg.shared.global [%0], [%1], 16, %2;"
        :: "r"(smem), "l"(gptr), "r"(szbytes) : "memory");
}
#define CP_COMMIT() asm volatile("cp.async.commit_group;" ::: "memory")
#define CP_WAIT0()  asm volatile("cp.async.wait_group 0;" ::: "memory")

// ---------------------------------------------------------------------------
// Kernel 1: geometry (count, camera inline) + weight fp16 convert, one launch.
//   blocks 0..111  : (bj, seg) projection count — proven math, exact JAX mirror
//   blocks 112..399: weight convert, layout [layer][tap][ic][oc]
// ---------------------------------------------------------------------------
__global__ void k_pre(const float* __restrict__ means,
                      const float* __restrict__ intr, const float* __restrict__ extr,
                      const float* __restrict__ w1, const float* __restrict__ w2)
{
    int bid = blockIdx.x;
    if (bid >= 112) {
        int idx = (bid - 112)*256 + threadIdx.x;   // < 73728 exactly
        int layer = idx / 36864; int rem = idx - layer*36864;
        int tap = rem >> 12;
        int ic = (rem >> 6) & 63, oc = rem & 63;
        const float* w = layer ? w2 : w1;
        g_wh[idx] = __float2half(w[(oc*64 + ic)*9 + tap]);
        return;
    }
    int bj = bid >> 2, seg = bid & 3;
    int b = bj / VP, j = bj % VP, k = j + 1;
    __shared__ float cm[24];
    __shared__ int s_cnt;
    if (threadIdx.x == 0) {
        const float* E = extr + (b*Vv + k)*16;
        const float* K = intr + (b*Vv + k)*9;
        float m[16], inv[16];
        #pragma unroll
        for (int i = 0; i < 16; ++i) m[i] = E[i];
        inv[0]  =  m[5]*m[10]*m[15] - m[5]*m[11]*m[14] - m[9]*m[6]*m[15] + m[9]*m[7]*m[14] + m[13]*m[6]*m[11] - m[13]*m[7]*m[10];
        inv[4]  = -m[4]*m[10]*m[15] + m[4]*m[11]*m[14] + m[8]*m[6]*m[15] - m[8]*m[7]*m[14] - m[12]*m[6]*m[11] + m[12]*m[7]*m[10];
        inv[8]  =  m[4]*m[9]*m[15]  - m[4]*m[11]*m[13] - m[8]*m[5]*m[15] + m[8]*m[7]*m[13] + m[12]*m[5]*m[11] - m[12]*m[7]*m[9];
        inv[12] = -m[4]*m[9]*m[14]  + m[4]*m[10]*m[13] + m[8]*m[5]*m[14] - m[8]*m[6]*m[13] - m[12]*m[5]*m[10] + m[12]*m[6]*m[9];
        inv[1]  = -m[1]*m[10]*m[15] + m[1]*m[11]*m[14] + m[9]*m[2]*m[15] - m[9]*m[3]*m[14] - m[13]*m[2]*m[11] + m[13]*m[3]*m[10];
        inv[5]  =  m[0]*m[10]*m[15] - m[0]*m[11]*m[14] - m[8]*m[2]*m[15] + m[8]*m[3]*m[14] + m[12]*m[2]*m[11] - m[12]*m[3]*m[10];
        inv[9]  = -m[0]*m[9]*m[15]  + m[0]*m[11]*m[13] + m[8]*m[1]*m[15] - m[8]*m[3]*m[13] - m[12]*m[1]*m[11] + m[12]*m[3]*m[9];
        inv[13] =  m[0]*m[9]*m[14]  - m[0]*m[10]*m[13] - m[8]*m[1]*m[14] + m[8]*m[2]*m[13] + m[12]*m[1]*m[10] - m[12]*m[2]*m[9];
        inv[2]  =  m[1]*m[6]*m[15]  - m[1]*m[7]*m[14]  - m[5]*m[2]*m[15] + m[5]*m[3]*m[14] + m[13]*m[2]*m[7]  - m[13]*m[3]*m[6];
        inv[6]  = -m[0]*m[6]*m[15]  + m[0]*m[7]*m[14]  + m[4]*m[2]*m[15] - m[4]*m[3]*m[14] - m[12]*m[2]*m[7]  + m[12]*m[3]*m[6];
        inv[10] =  m[0]*m[5]*m[15]  - m[0]*m[7]*m[13]  - m[4]*m[1]*m[15] + m[4]*m[3]*m[13] + m[12]*m[1]*m[7]  - m[12]*m[3]*m[5];
        inv[14] = -m[0]*m[5]*m[14]  + m[0]*m[6]*m[13]  + m[4]*m[1]*m[14] - m[4]*m[2]*m[13] - m[12]*m[1]*m[6]  + m[12]*m[2]*m[5];
        inv[3]  = -m[1]*m[6]*m[11]  + m[1]*m[7]*m[10]  + m[5]*m[2]*m[11] - m[5]*m[3]*m[10] - m[9]*m[2]*m[7]   + m[9]*m[3]*m[6];
        inv[7]  =  m[0]*m[6]*m[11]  - m[0]*m[7]*m[10]  - m[4]*m[2]*m[11] + m[4]*m[3]*m[10] + m[8]*m[2]*m[7]   - m[8]*m[3]*m[6];
        inv[11] = -m[0]*m[5]*m[11]  + m[0]*m[7]*m[9]   + m[4]*m[1]*m[11] - m[4]*m[3]*m[9]  - m[8]*m[1]*m[7]   + m[8]*m[3]*m[5];
        inv[15] =  m[0]*m[5]*m[10]  - m[0]*m[6]*m[9]   - m[4]*m[1]*m[10] + m[4]*m[2]*m[9]  + m[8]*m[1]*m[6]   - m[8]*m[2]*m[5];
        float det = m[0]*inv[0] + m[1]*inv[4] + m[2]*inv[8] + m[3]*inv[12];
        float id = 1.0f / det;
        #pragma unroll
        for (int i = 0; i < 12; ++i) cm[i] = inv[i]*id;
        #pragma unroll
        for (int i = 0; i < 9; ++i) cm[12 + i] = K[i];
        s_cnt = 0;
    }
    __syncthreads();
    const float* mb = means + (size_t)(b*Vv + j)*HW*3;
    int cnt = 0;
    int i0 = seg * 4096;
    for (int i = i0 + threadIdx.x; i < i0 + 4096; i += blockDim.x) {
        float x = mb[i*3+0], y = mb[i*3+1], z = mb[i*3+2];
        float c0 = __fadd_rn(__fadd_rn(__fadd_rn(__fmul_rn(cm[0],x), __fmul_rn(cm[1],y)), __fmul_rn(cm[2],z)), cm[3]);
        float c1 = __fadd_rn(__fadd_rn(__fadd_rn(__fmul_rn(cm[4],x), __fmul_rn(cm[5],y)), __fmul_rn(cm[6],z)), cm[7]);
        float c2 = __fadd_rn(__fadd_rn(__fadd_rn(__fmul_rn(cm[8],x), __fmul_rn(cm[9],y)), __fmul_rn(cm[10],z)), cm[11]);
        float p0 = __fadd_rn(__fadd_rn(__fmul_rn(cm[12],c0), __fmul_rn(cm[13],c1)), __fmul_rn(cm[14],c2));
        float p1 = __fadd_rn(__fadd_rn(__fmul_rn(cm[15],c0), __fmul_rn(cm[16],c1)), __fmul_rn(cm[17],c2));
        float p2 = __fadd_rn(__fadd_rn(__fmul_rn(cm[18],c0), __fmul_rn(cm[19],c1)), __fmul_rn(cm[20],c2));
        float d  = __fadd_rn(p2, 1e-8f);
        float nx = p0 / d, ny = p1 / d;
        bool valid = (nx >= 0.f) && (nx < 1.f) && (ny >= 0.f) && (ny < 1.f) && (c2 > 1e-8f);
        int px = (int)floorf(__fmul_rn(nx, 128.f)); px = min(max(px, 0), 127);
        int py = (int)floorf(__fmul_rn(ny, 128.f)); py = min(max(py, 0), 127);
        g_src[bj*HW + i] = valid ? (py*128 + px) : -1;
        cnt += valid ? 1 : 0;
    }
    atomicAdd(&s_cnt, cnt);
    __syncthreads();
    if (threadIdx.x == 0) atomicAdd(&g_cnt[bj], s_cnt);
}

// ---------------------------------------------------------------------------
// Kernel 2: fuse -> NHWC fp16 (unchanged numerics)
// ---------------------------------------------------------------------------
__global__ __launch_bounds__(256)
void k_fuse2(const float* __restrict__ gsf)
{
    int y = blockIdx.x, n = blockIdx.y;
    int b = n >> 3, view = n & 7;
    __shared__ int S[128];
    __shared__ float s_w;
    int tid = threadIdx.x;
    if (view < VP) {
        int bj = b*VP + view;
        if (tid < 128) S[tid] = g_src[bj*HW + y*128 + tid];
        if (tid == 0) s_w = (0.1f / (float)HW) * (float)g_cnt[bj];
    } else {
        if (tid < 128) S[tid] = -1;
        if (tid == 0) s_w = 0.f;
    }
    __syncthreads();
    float wg = s_w, iw = 1.f / (1.f + wg);
    const float* fj = gsf + ((size_t)n*HW + (size_t)y*128)*64;
    const float* fk = gsf + (size_t)(n+1)*HW*64;
    size_t ob = ((size_t)n*HW + (size_t)y*128)*64;
    #pragma unroll
    for (int i = 0; i < 8; ++i) {
        int idx = tid + i*256;
        int px = idx >> 4, c4 = (idx & 15)*4;
        float4 a = *(const float4*)(fj + px*64 + c4);
        int s = S[px];
        float4 g = make_float4(0.f,0.f,0.f,0.f);
        if (s >= 0) g = *(const float4*)(fk + (size_t)s*64 + c4);
        float v0 = (a.x + g.x*wg)*iw, v1 = (a.y + g.y*wg)*iw;
        float v2 = (a.z + g.z*wg)*iw, v3 = (a.w + g.w*wg)*iw;
        uint2 ph;
        ph.x = (u32)__half_as_ushort(__float2half(v0)) | ((u32)__half_as_ushort(__float2half(v1)) << 16);
        ph.y = (u32)__half_as_ushort(__float2half(v2)) | ((u32)__half_as_ushort(__float2half(v3)) << 16);
        *(uint2*)(g_fh + ob + px*64 + c4) = ph;
    }
}

// ---------------------------------------------------------------------------
// Kernel 3/4: mma.sync fp16 single-term conv, row-paired, cp.async staging.
// grid(2 ochalf, 2 slab, 32 img), 256 threads = 8 warps, warp 16px x 32oc x 2rows.
// SMEM: B 9 tiles [64ic x 32oc] stride 80B = 46080B;
//       A ring 6 slots x [130 rows x 64ic] stride 144B = 112320B.
// ---------------------------------------------------------------------------
#define BTILE 5120u
#define AROW 144u
#define ASLOT 18720u
#define BOFF_SZ 46080u
#define SMEM_REQ 158400

template<bool FIRST>
__global__ void __launch_bounds__(256, 1) k_conv_mma(
    const __half* __restrict__ inh, const float* __restrict__ bias,
    __half* __restrict__ outh, float* __restrict__ outf,
    const __half* __restrict__ wh)
{
    extern __shared__ char dsm[];
    u32 sb = s2u(dsm);
    u32 Boff = sb, Aoff = sb + BOFF_SZ;

    int ochalf = blockIdx.x, slab = blockIdx.y, n = blockIdx.z;
    int oc0 = ochalf*32, ybase = slab*64;
    int tid = threadIdx.x, wid = tid >> 5, t = tid & 31;
    int px0 = wid*16;

    // ---- B build: 9 tap tiles, stride-80 rows ----
    #pragma unroll
    for (int i = 0; i < 9; ++i) {
        int c = tid + i*256;
        int tap = c >> 8;
        int rem = c & 255;
        int ic = rem >> 2, q = rem & 3;
        uint4 v = *(const uint4*)(wh + ((size_t)tap*64 + ic)*64 + oc0 + q*8);
        *(uint4*)(dsm + (u32)tap*BTILE + (u32)ic*80u + (u32)q*16u) = v;
    }
    // ---- zero halo rows 0 and 129 of all 6 slots ----
    if (tid < 108) {
        int slot = tid / 18, rem = tid % 18;
        int rr = rem / 9, q = rem % 9;
        u32 off = BOFF_SZ + (u32)slot*ASLOT + (rr ? 129u*AROW : 0u) + (u32)q*16u;
        *(uint4*)(dsm + off) = make_uint4(0,0,0,0);
    }
    // ---- prologue: build rows ybase-1 .. ybase+2 ----
    for (int r = ybase-1; r <= ybase+2; ++r) {
        int slot = (r + 6) % 6;
        u32 base = BOFF_SZ + (u32)slot*ASLOT;
        bool vr = ((unsigned)r < 128u);
        #pragma unroll
        for (int i = 0; i < 4; ++i) {
            int c = tid + i*256;           // 1024 chunks of 16B
            int px = c >> 3, q = c & 7;
            uint4 v = make_uint4(0,0,0,0);
            if (vr) v = *(const uint4*)(inh + ((size_t)n*HW + (size_t)r*128 + px)*64 + q*8);
            *(uint4*)(dsm + base + (u32)(px+1)*AROW + (u32)q*16u) = v;
        }
    }
    // per-thread bias regs
    float bo0[4], bo1[4];
    #pragma unroll
    for (int nb = 0; nb < 4; ++nb) {
        int oc = oc0 + nb*8 + (t & 3)*2;
        bo0[nb] = bias[oc];
        bo1[nb] = bias[oc + 1];
    }
    __syncthreads();

    u32 laneA = (u32)(t & 15)*AROW + (u32)((t >> 4) << 4);
    u32 laneB = (u32)(t & 15)*80u  + (u32)((t >> 4) << 4);
    int myc = tid;                 // this thread's staging chunk id base
    int mypx = myc >> 3, myq = myc & 7;

    #pragma unroll 1
    for (int it = 0; it < 32; ++it) {
        int gy = ybase + it*2;
        // ---- stage rows gy+3, gy+4 via cp.async into slots (gy-3)%6,(gy-2)%6 ----
        #pragma unroll
        for (int rr = 0; rr < 2; ++rr) {
            int r = gy + 3 + rr;
            int sz = (r <= 127) ? 16 : 0;
            u32 base = Aoff + (u32)((r + 6) % 6)*ASLOT;
            const __half* gsrc = inh + ((size_t)n*HW + (size_t)r*128)*64;
            #pragma unroll
            for (int i = 0; i < 4; ++i) {
                int px = mypx + i*32, q = myq;
                cp_async16(base + (u32)(px+1)*AROW + (u32)q*16u,
                           gsrc + (size_t)px*64 + q*8, sz);
            }
        }
        CP_COMMIT();
        // ---- compute rows gy, gy+1 ----
        float acc[2][4][4];
        #pragma unroll
        for (int r = 0; r < 2; ++r)
            #pragma unroll
            for (int nb = 0; nb < 4; ++nb)
                #pragma unroll
                for (int i = 0; i < 4; ++i) acc[r][nb][i] = 0.f;

        u32 abase[4];
        #pragma unroll
        for (int ar = 0; ar < 4; ++ar)
            abase[ar] = Aoff + (u32)((gy - 1 + ar + 6) % 6)*ASLOT;

        #pragma unroll
        for (int dx = 0; dx < 3; ++dx) {
            #pragma unroll
            for (int kc = 0; kc < 4; ++kc) {
                u32 B[3][8];
                #pragma unroll
                for (int dy = 0; dy < 3; ++dy) {
                    u32 bb = Boff + (u32)(dy*3 + dx)*BTILE + laneB + (u32)kc*1280u;
                    ldsm4t(B[dy],     bb);
                    ldsm4t(B[dy] + 4, bb + 32u);
                }
                #pragma unroll
                for (int ar = 0; ar < 4; ++ar) {
                    u32 Af[4];
                    ldsm4(Af, abase[ar] + (u32)(px0 + dx)*AROW + laneA + (u32)kc*32u);
                    if (ar < 3) {
                        #pragma unroll
                        for (int nb = 0; nb < 4; ++nb)
                            mma_fp16(acc[0][nb], Af, &B[ar][nb*2]);
                    }
                    if (ar > 0) {
                        #pragma unroll
                        for (int nb = 0; nb < 4; ++nb)
                            mma_fp16(acc[1][nb], Af, &B[ar-1][nb*2]);
                    }
                }
            }
        }
        // ---- epilogue: bias (+gelu), store rows gy, gy+1 ----
        #pragma unroll
        for (int r = 0; r < 2; ++r) {
            int gyr = gy + r;
            #pragma unroll
            for (int nb = 0; nb < 4; ++nb) {
                int oc = oc0 + nb*8 + (t & 3)*2;
                #pragma unroll
                for (int rg = 0; rg < 2; ++rg) {
                    int px = px0 + (t >> 2) + rg*8;
                    float v0 = acc[r][nb][rg*2]   + bo0[nb];
                    float v1 = acc[r][nb][rg*2+1] + bo1[nb];
                    size_t base = ((size_t)n*HW + (size_t)gyr*128 + px)*64 + oc;
                    if (FIRST) {
                        v0 = 0.5f * v0 * (1.0f + erff(v0 * 0.70710678118654752f));
                        v1 = 0.5f * v1 * (1.0f + erff(v1 * 0.70710678118654752f));
                        u32 hp = (u32)__half_as_ushort(__float2half(v0))
                               | ((u32)__half_as_ushort(__float2half(v1)) << 16);
                        *(u32*)(outh + base) = hp;
                    } else {
                        *(float2*)(outf + base) = make_float2(v0, v1);
                    }
                }
            }
        }
        // ---- wait staged rows, single barrier ----
        CP_WAIT0();
        __syncthreads();
    }
}

// ---------------------------------------------------------------------------
extern "C" void kernel_launch(void* const* d_in, const int* in_sizes, int n_in,
                              void* d_out, int out_size)
{
    const float* means = (const float*)d_in[0];
    const float* gsf   = (const float*)d_in[2];
    const float* intr  = (const float*)d_in[3];
    const float* extr  = (const float*)d_in[4];
    const float* w1    = (const float*)d_in[5];
    const float* b1    = (const float*)d_in[6];
    const float* w2    = (const float*)d_in[7];
    const float* b2    = (const float*)d_in[8];
    float* out = (float*)d_out;

    __half *pfh, *pmh, *pwh;
    int* pcnt;
    cudaGetSymbolAddress((void**)&pfh, g_fh);
    cudaGetSymbolAddress((void**)&pmh, g_mh);
    cudaGetSymbolAddress((void**)&pwh, g_wh);
    cudaGetSymbolAddress((void**)&pcnt, g_cnt);

    cudaFuncSetAttribute(k_conv_mma<true>,  cudaFuncAttributeMaxDynamicSharedMemorySize, SMEM_REQ);
    cudaFuncSetAttribute(k_conv_mma<false>, cudaFuncAttributeMaxDynamicSharedMemorySize, SMEM_REQ);

    cudaMemsetAsync(pcnt, 0, NBJ*sizeof(int), 0);
    k_pre<<<400, 256>>>(means, intr, extr, w1, w2);
    k_fuse2<<<dim3(128, 32), 256>>>(gsf);
    k_conv_mma<true ><<<dim3(2, 2, 32), 256, SMEM_REQ>>>(pfh, b1, pmh, nullptr, pwh);
    k_conv_mma<false><<<dim3(2, 2, 32), 256, SMEM_REQ>>>(pmh, b2, nullptr, out, pwh + 9*64*64);
}

// round 12
// speedup vs baseline: 9.5925x; 1.0144x over previous
#include <cuda_runtime.h>
#include <cuda_fp16.h>
#include <math.h>
#include <stdint.h>

#define Bv 4
#define Vv 8
#define HW 16384
#define VP 7
#define NBJ 28
#define NIMG 32
typedef unsigned long long u64;
typedef uint32_t u32;

// ------------------------- device scratch -------------------------
__device__ __half g_fh[NIMG*HW*64];   // fused features fp16, NHWC
__device__ __half g_mh[NIMG*HW*64];   // gelu(conv1) fp16, NHWC
__device__ __half g_wh[2*9*64*64];    // [layer][tap][ic][oc] fp16
__device__ int   g_src[NBJ*HW];
__device__ int   g_cnt[NBJ];

// ------------------------- PTX helpers -------------------------
__device__ __forceinline__ u32 s2u(const void* p) {
    u32 a;
    asm("{ .reg .u64 t; cvta.to.shared.u64 t, %1; cvt.u32.u64 %0, t; }" : "=r"(a) : "l"(p));
    return a;
}
__device__ __forceinline__ void ldsm4(u32* r, u32 addr) {
    asm volatile("ldmatrix.sync.aligned.m8n8.x4.shared.b16 {%0,%1,%2,%3}, [%4];"
        : "=r"(r[0]), "=r"(r[1]), "=r"(r[2]), "=r"(r[3]) : "r"(addr));
}
__device__ __forceinline__ void ldsm4t(u32* r, u32 addr) {
    asm volatile("ldmatrix.sync.aligned.m8n8.x4.trans.shared.b16 {%0,%1,%2,%3}, [%4];"
        : "=r"(r[0]), "=r"(r[1]), "=r"(r[2]), "=r"(r[3]) : "r"(addr));
}
__device__ __forceinline__ void mma_fp16(float* d, const u32* a, const u32* b) {
    asm volatile("mma.sync.aligned.m16n8k16.row.col.f32.f16.f16.f32 "
        "{%0,%1,%2,%3}, {%4,%5,%6,%7}, {%8,%9}, {%0,%1,%2,%3};"
        : "+f"(d[0]), "+f"(d[1]), "+f"(d[2]), "+f"(d[3])
        : "r"(a[0]), "r"(a[1]), "r"(a[2]), "r"(a[3]), "r"(b[0]), "r"(b[1]));
}
__device__ __forceinline__ void cp_async16(u32 smem, const void* gptr, int szbytes) {
    asm volatile("cp.async.cg.shared.global [%0], [%1], 16, %2;"
        :: "r"(smem), "l"(gptr), "r"(szbytes) : "memory");
}
#define CP_COMMIT() asm volatile("cp.async.commit_group;" ::: "memory")
#define CP_WAIT0()  asm volatile("cp.async.wait_group 0;" ::: "memory")

// ---------------------------------------------------------------------------
// Kernel 1: geometry (count, camera inline) + weight fp16 convert, one launch.
// ---------------------------------------------------------------------------
__global__ void k_pre(const float* __restrict__ means,
                      const float* __restrict__ intr, const float* __restrict__ extr,
                      const float* __restrict__ w1, const float* __restrict__ w2)
{
    int bid = blockIdx.x;
    if (bid >= 112) {
        int idx = (bid - 112)*256 + threadIdx.x;   // < 73728 exactly
        int layer = idx / 36864; int rem = idx - layer*36864;
        int tap = rem >> 12;
        int ic = (rem >> 6) & 63, oc = rem & 63;
        const float* w = layer ? w2 : w1;
        g_wh[idx] = __float2half(w[(oc*64 + ic)*9 + tap]);
        return;
    }
    int bj = bid >> 2, seg = bid & 3;
    int b = bj / VP, j = bj % VP, k = j + 1;
    __shared__ float cm[24];
    __shared__ int s_cnt;
    if (threadIdx.x == 0) {
        const float* E = extr + (b*Vv + k)*16;
        const float* K = intr + (b*Vv + k)*9;
        float m[16], inv[16];
        #pragma unroll
        for (int i = 0; i < 16; ++i) m[i] = E[i];
        inv[0]  =  m[5]*m[10]*m[15] - m[5]*m[11]*m[14] - m[9]*m[6]*m[15] + m[9]*m[7]*m[14] + m[13]*m[6]*m[11] - m[13]*m[7]*m[10];
        inv[4]  = -m[4]*m[10]*m[15] + m[4]*m[11]*m[14] + m[8]*m[6]*m[15] - m[8]*m[7]*m[14] - m[12]*m[6]*m[11] + m[12]*m[7]*m[10];
        inv[8]  =  m[4]*m[9]*m[15]  - m[4]*m[11]*m[13] - m[8]*m[5]*m[15] + m[8]*m[7]*m[13] + m[12]*m[5]*m[11] - m[12]*m[7]*m[9];
        inv[12] = -m[4]*m[9]*m[14]  + m[4]*m[10]*m[13] + m[8]*m[5]*m[14] - m[8]*m[6]*m[13] - m[12]*m[5]*m[10] + m[12]*m[6]*m[9];
        inv[1]  = -m[1]*m[10]*m[15] + m[1]*m[11]*m[14] + m[9]*m[2]*m[15] - m[9]*m[3]*m[14] - m[13]*m[2]*m[11] + m[13]*m[3]*m[10];
        inv[5]  =  m[0]*m[10]*m[15] - m[0]*m[11]*m[14] - m[8]*m[2]*m[15] + m[8]*m[3]*m[14] + m[12]*m[2]*m[11] - m[12]*m[3]*m[10];
        inv[9]  = -m[0]*m[9]*m[15]  + m[0]*m[11]*m[13] + m[8]*m[1]*m[15] - m[8]*m[3]*m[13] - m[12]*m[1]*m[11] + m[12]*m[3]*m[9];
        inv[13] =  m[0]*m[9]*m[14]  - m[0]*m[10]*m[13] - m[8]*m[1]*m[14] + m[8]*m[2]*m[13] + m[12]*m[1]*m[10] - m[12]*m[2]*m[9];
        inv[2]  =  m[1]*m[6]*m[15]  - m[1]*m[7]*m[14]  - m[5]*m[2]*m[15] + m[5]*m[3]*m[14] + m[13]*m[2]*m[7]  - m[13]*m[3]*m[6];
        inv[6]  = -m[0]*m[6]*m[15]  + m[0]*m[7]*m[14]  + m[4]*m[2]*m[15] - m[4]*m[3]*m[14] - m[12]*m[2]*m[7]  + m[12]*m[3]*m[6];
        inv[10] =  m[0]*m[5]*m[15]  - m[0]*m[7]*m[13]  - m[4]*m[1]*m[15] + m[4]*m[3]*m[13] + m[12]*m[1]*m[7]  - m[12]*m[3]*m[5];
        inv[14] = -m[0]*m[5]*m[14]  + m[0]*m[6]*m[13]  + m[4]*m[1]*m[14] - m[4]*m[2]*m[13] - m[12]*m[1]*m[6]  + m[12]*m[2]*m[5];
        inv[3]  = -m[1]*m[6]*m[11]  + m[1]*m[7]*m[10]  + m[5]*m[2]*m[11] - m[5]*m[3]*m[10] - m[9]*m[2]*m[7]   + m[9]*m[3]*m[6];
        inv[7]  =  m[0]*m[6]*m[11]  - m[0]*m[7]*m[10]  - m[4]*m[2]*m[11] + m[4]*m[3]*m[10] + m[8]*m[2]*m[7]   - m[8]*m[3]*m[6];
        inv[11] = -m[0]*m[5]*m[11]  + m[0]*m[7]*m[9]   + m[4]*m[1]*m[11] - m[4]*m[3]*m[9]  - m[8]*m[1]*m[7]   + m[8]*m[3]*m[5];
        inv[15] =  m[0]*m[5]*m[10]  - m[0]*m[6]*m[9]   - m[4]*m[1]*m[10] + m[4]*m[2]*m[9]  + m[8]*m[1]*m[6]   - m[8]*m[2]*m[5];
        float det = m[0]*inv[0] + m[1]*inv[4] + m[2]*inv[8] + m[3]*inv[12];
        float id = 1.0f / det;
        #pragma unroll
        for (int i = 0; i < 12; ++i) cm[i] = inv[i]*id;
        #pragma unroll
        for (int i = 0; i < 9; ++i) cm[12 + i] = K[i];
        s_cnt = 0;
    }
    __syncthreads();
    const float* mb = means + (size_t)(b*Vv + j)*HW*3;
    int cnt = 0;
    int i0 = seg * 4096;
    for (int i = i0 + threadIdx.x; i < i0 + 4096; i += blockDim.x) {
        float x = mb[i*3+0], y = mb[i*3+1], z = mb[i*3+2];
        float c0 = __fadd_rn(__fadd_rn(__fadd_rn(__fmul_rn(cm[0],x), __fmul_rn(cm[1],y)), __fmul_rn(cm[2],z)), cm[3]);
        float c1 = __fadd_rn(__fadd_rn(__fadd_rn(__fmul_rn(cm[4],x), __fmul_rn(cm[5],y)), __fmul_rn(cm[6],z)), cm[7]);
        float c2 = __fadd_rn(__fadd_rn(__fadd_rn(__fmul_rn(cm[8],x), __fmul_rn(cm[9],y)), __fmul_rn(cm[10],z)), cm[11]);
        float p0 = __fadd_rn(__fadd_rn(__fmul_rn(cm[12],c0), __fmul_rn(cm[13],c1)), __fmul_rn(cm[14],c2));
        float p1 = __fadd_rn(__fadd_rn(__fmul_rn(cm[15],c0), __fmul_rn(cm[16],c1)), __fmul_rn(cm[17],c2));
        float p2 = __fadd_rn(__fadd_rn(__fmul_rn(cm[18],c0), __fmul_rn(cm[19],c1)), __fmul_rn(cm[20],c2));
        float d  = __fadd_rn(p2, 1e-8f);
        float nx = p0 / d, ny = p1 / d;
        bool valid = (nx >= 0.f) && (nx < 1.f) && (ny >= 0.f) && (ny < 1.f) && (c2 > 1e-8f);
        int px = (int)floorf(__fmul_rn(nx, 128.f)); px = min(max(px, 0), 127);
        int py = (int)floorf(__fmul_rn(ny, 128.f)); py = min(max(py, 0), 127);
        g_src[bj*HW + i] = valid ? (py*128 + px) : -1;
        cnt += valid ? 1 : 0;
    }
    atomicAdd(&s_cnt, cnt);
    __syncthreads();
    if (threadIdx.x == 0) atomicAdd(&g_cnt[bj], s_cnt);
}

// ---------------------------------------------------------------------------
// Kernel 2: fuse -> NHWC fp16 (unchanged numerics)
// ---------------------------------------------------------------------------
__global__ __launch_bounds__(256)
void k_fuse2(const float* __restrict__ gsf)
{
    int y = blockIdx.x, n = blockIdx.y;
    int b = n >> 3, view = n & 7;
    __shared__ int S[128];
    __shared__ float s_w;
    int tid = threadIdx.x;
    if (view < VP) {
        int bj = b*VP + view;
        if (tid < 128) S[tid] = g_src[bj*HW + y*128 + tid];
        if (tid == 0) s_w = (0.1f / (float)HW) * (float)g_cnt[bj];
    } else {
        if (tid < 128) S[tid] = -1;
        if (tid == 0) s_w = 0.f;
    }
    __syncthreads();
    float wg = s_w, iw = 1.f / (1.f + wg);
    const float* fj = gsf + ((size_t)n*HW + (size_t)y*128)*64;
    const float* fk = gsf + (size_t)(n+1)*HW*64;
    size_t ob = ((size_t)n*HW + (size_t)y*128)*64;
    #pragma unroll
    for (int i = 0; i < 8; ++i) {
        int idx = tid + i*256;
        int px = idx >> 4, c4 = (idx & 15)*4;
        float4 a = *(const float4*)(fj + px*64 + c4);
        int s = S[px];
        float4 g = make_float4(0.f,0.f,0.f,0.f);
        if (s >= 0) g = *(const float4*)(fk + (size_t)s*64 + c4);
        float v0 = (a.x + g.x*wg)*iw, v1 = (a.y + g.y*wg)*iw;
        float v2 = (a.z + g.z*wg)*iw, v3 = (a.w + g.w*wg)*iw;
        uint2 ph;
        ph.x = (u32)__half_as_ushort(__float2half(v0)) | ((u32)__half_as_ushort(__float2half(v1)) << 16);
        ph.y = (u32)__half_as_ushort(__float2half(v2)) | ((u32)__half_as_ushort(__float2half(v3)) << 16);
        *(uint2*)(g_fh + ob + px*64 + c4) = ph;
    }
}

// ---------------------------------------------------------------------------
// Kernel 3/4: mma.sync fp16 single-term conv, row-paired, cp.async staging.
// 64px-wide blocks for 2 blocks/SM co-residency.
// grid(4 = xhalf*2+ochalf, 2 slab, 32 img), 128 threads = 4 warps,
// warp tile 16px x 32oc x 2 rows. Per-warp math identical to R10/R11.
// SMEM: B 9 tiles [64ic x 32oc] stride 80B = 46080B;
//       A ring 6 slots x [66 entries x 64ic] stride 144B = 57024B. Total 103104B.
// ---------------------------------------------------------------------------
#define BTILE 5120u
#define AROW 144u
#define ASLOT 9504u
#define BOFF_SZ 46080u
#define SMEM_REQ 103104

template<bool FIRST>
__global__ void __launch_bounds__(128, 2) k_conv_mma(
    const __half* __restrict__ inh, const float* __restrict__ bias,
    __half* __restrict__ outh, float* __restrict__ outf,
    const __half* __restrict__ wh)
{
    extern __shared__ char dsm[];
    u32 sb = s2u(dsm);
    u32 Boff = sb, Aoff = sb + BOFF_SZ;

    int xh = blockIdx.x >> 1, ochalf = blockIdx.x & 1;
    int slab = blockIdx.y, n = blockIdx.z;
    int x0 = xh*64, oc0 = ochalf*32, ybase = slab*64;
    int tid = threadIdx.x, wid = tid >> 5, t = tid & 31;
    int px0 = wid*16;                       // local px base of warp tile

    // ---- B build: 9 tap tiles, stride-80 rows (2304 chunks, 128 thr) ----
    #pragma unroll
    for (int i = 0; i < 18; ++i) {
        int c = tid + i*128;
        int tap = c >> 8;
        int rem = c & 255;
        int ic = rem >> 2, q = rem & 3;
        uint4 v = *(const uint4*)(wh + ((size_t)tap*64 + ic)*64 + oc0 + q*8);
        *(uint4*)(dsm + (u32)tap*BTILE + (u32)ic*80u + (u32)q*16u) = v;
    }
    // ---- prologue: build rows ybase-1 .. ybase+2 (528 chunks each) ----
    for (int r = ybase-1; r <= ybase+2; ++r) {
        int slot = (r + 6) % 6;
        u32 base = BOFF_SZ + (u32)slot*ASLOT;
        bool vr = ((unsigned)r < 128u);
        #pragma unroll
        for (int i = 0; i < 5; ++i) {
            int c = tid + i*128;
            if (c < 528) {
                int e = c >> 3, q = c & 7;       // entry 0..65, quarter
                int gpx = x0 + e - 1;
                uint4 v = make_uint4(0,0,0,0);
                if (vr && (unsigned)gpx < 128u)
                    v = *(const uint4*)(inh + ((size_t)n*HW + (size_t)r*128 + gpx)*64 + q*8);
                *(uint4*)(dsm + base + (u32)e*AROW + (u32)q*16u) = v;
            }
        }
    }
    // per-thread bias regs
    float bo0[4], bo1[4];
    #pragma unroll
    for (int nb = 0; nb < 4; ++nb) {
        int oc = oc0 + nb*8 + (t & 3)*2;
        bo0[nb] = bias[oc];
        bo1[nb] = bias[oc + 1];
    }
    __syncthreads();

    u32 laneA = (u32)(t & 15)*AROW + (u32)((t >> 4) << 4);
    u32 laneB = (u32)(t & 15)*80u  + (u32)((t >> 4) << 4);

    #pragma unroll 1
    for (int it = 0; it < 32; ++it) {
        int gy = ybase + it*2;
        // ---- stage rows gy+3, gy+4 via cp.async into slots (gy+3)%6,(gy+4)%6 ----
        #pragma unroll
        for (int rr = 0; rr < 2; ++rr) {
            int r = gy + 3 + rr;
            bool vr = (r <= 127);
            int rc = vr ? r : 127;
            u32 base = Aoff + (u32)((r + 6) % 6)*ASLOT;
            const __half* gsrc = inh + ((size_t)n*HW + (size_t)rc*128)*64;
            #pragma unroll
            for (int i = 0; i < 5; ++i) {
                int c = tid + i*128;
                if (c < 528) {
                    int e = c >> 3, q = c & 7;
                    int gpx = x0 + e - 1;
                    bool vp = ((unsigned)gpx < 128u);
                    int gpxc = vp ? gpx : 0;
                    cp_async16(base + (u32)e*AROW + (u32)q*16u,
                               gsrc + (size_t)gpxc*64 + q*8, (vr && vp) ? 16 : 0);
                }
            }
        }
        CP_COMMIT();
        // ---- compute rows gy, gy+1 ----
        float acc[2][4][4];
        #pragma unroll
        for (int r = 0; r < 2; ++r)
            #pragma unroll
            for (int nb = 0; nb < 4; ++nb)
                #pragma unroll
                for (int i = 0; i < 4; ++i) acc[r][nb][i] = 0.f;

        u32 abase[4];
        #pragma unroll
        for (int ar = 0; ar < 4; ++ar)
            abase[ar] = Aoff + (u32)((gy - 1 + ar + 6) % 6)*ASLOT;

        #pragma unroll
        for (int dx = 0; dx < 3; ++dx) {
            #pragma unroll
            for (int kc = 0; kc < 4; ++kc) {
                u32 B[3][8];
                #pragma unroll
                for (int dy = 0; dy < 3; ++dy) {
                    u32 bb = Boff + (u32)(dy*3 + dx)*BTILE + laneB + (u32)kc*1280u;
                    ldsm4t(B[dy],     bb);
                    ldsm4t(B[dy] + 4, bb + 32u);
                }
                #pragma unroll
                for (int ar = 0; ar < 4; ++ar) {
                    u32 Af[4];
                    ldsm4(Af, abase[ar] + (u32)(px0 + dx)*AROW + laneA + (u32)kc*32u);
                    if (ar < 3) {
                        #pragma unroll
                        for (int nb = 0; nb < 4; ++nb)
                            mma_fp16(acc[0][nb], Af, &B[ar][nb*2]);
                    }
                    if (ar > 0) {
                        #pragma unroll
                        for (int nb = 0; nb < 4; ++nb)
                            mma_fp16(acc[1][nb], Af, &B[ar-1][nb*2]);
                    }
                }
            }
        }
        // ---- epilogue: bias (+gelu), store rows gy, gy+1 ----
        #pragma unroll
        for (int r = 0; r < 2; ++r) {
            int gyr = gy + r;
            #pragma unroll
            for (int nb = 0; nb < 4; ++nb) {
                int oc = oc0 + nb*8 + (t & 3)*2;
                #pragma unroll
                for (int rg = 0; rg < 2; ++rg) {
                    int px = x0 + px0 + (t >> 2) + rg*8;
                    float v0 = acc[r][nb][rg*2]   + bo0[nb];
                    float v1 = acc[r][nb][rg*2+1] + bo1[nb];
                    size_t base = ((size_t)n*HW + (size_t)gyr*128 + px)*64 + oc;
                    if (FIRST) {
                        v0 = 0.5f * v0 * (1.0f + erff(v0 * 0.70710678118654752f));
                        v1 = 0.5f * v1 * (1.0f + erff(v1 * 0.70710678118654752f));
                        u32 hp = (u32)__half_as_ushort(__float2half(v0))
                               | ((u32)__half_as_ushort(__float2half(v1)) << 16);
                        *(u32*)(outh + base) = hp;
                    } else {
                        *(float2*)(outf + base) = make_float2(v0, v1);
                    }
                }
            }
        }
        // ---- wait staged rows, single barrier ----
        CP_WAIT0();
        __syncthreads();
    }
}

// ---------------------------------------------------------------------------
extern "C" void kernel_launch(void* const* d_in, const int* in_sizes, int n_in,
                              void* d_out, int out_size)
{
    const float* means = (const float*)d_in[0];
    const float* gsf   = (const float*)d_in[2];
    const float* intr  = (const float*)d_in[3];
    const float* extr  = (const float*)d_in[4];
    const float* w1    = (const float*)d_in[5];
    const float* b1    = (const float*)d_in[6];
    const float* w2    = (const float*)d_in[7];
    const float* b2    = (const float*)d_in[8];
    float* out = (float*)d_out;

    __half *pfh, *pmh, *pwh;
    int* pcnt;
    cudaGetSymbolAddress((void**)&pfh, g_fh);
    cudaGetSymbolAddress((void**)&pmh, g_mh);
    cudaGetSymbolAddress((void**)&pwh, g_wh);
    cudaGetSymbolAddress((void**)&pcnt, g_cnt);

    cudaFuncSetAttribute(k_conv_mma<true>,  cudaFuncAttributeMaxDynamicSharedMemorySize, SMEM_REQ);
    cudaFuncSetAttribute(k_conv_mma<false>, cudaFuncAttributeMaxDynamicSharedMemorySize, SMEM_REQ);

    cudaMemsetAsync(pcnt, 0, NBJ*sizeof(int), 0);
    k_pre<<<400, 256>>>(means, intr, extr, w1, w2);
    k_fuse2<<<dim3(128, 32), 256>>>(gsf);
    k_conv_mma<true ><<<dim3(4, 2, 32), 128, SMEM_REQ>>>(pfh, b1, pmh, nullptr, pwh);
    k_conv_mma<false><<<dim3(4, 2, 32), 128, SMEM_REQ>>>(pmh, b2, nullptr, out, pwh + 9*64*64);
}